// round 1
// baseline (speedup 1.0000x reference)
#include <cuda_runtime.h>
#include <math.h>

#define SEQ   2048
#define HID   1024
#define NH    16
#define DH    64
#define N_QKV 3072

// Scratch (allocation-free rule: __device__ globals)
__device__ __align__(16) float g_q[NH * SEQ * DH];
__device__ __align__(16) float g_k[NH * SEQ * DH];
__device__ __align__(16) float g_v[NH * SEQ * DH];
__device__ __align__(16) float g_ctx[SEQ * HID];

// ---------------------------------------------------------------------------
// Tiled SGEMM: C[64x64] per block, BK=16, 256 threads, 4x4 micro-tile.
// A row-major [M,K], B row-major [K,N]. Epilogue differs per kernel.
// ---------------------------------------------------------------------------

__global__ __launch_bounds__(256) void qkv_kernel(const float* __restrict__ A,
                                                  const float* __restrict__ Bm,
                                                  const float* __restrict__ bias) {
    __shared__ float As[16][68];   // transposed: As[k][m]
    __shared__ float Bs[16][64];
    const int K = HID, N = N_QKV;
    const int n0 = blockIdx.x * 64, m0 = blockIdx.y * 64;
    const int tid = threadIdx.x;
    const int tx = tid & 15, ty = tid >> 4;
    float acc[4][4] = {};
    for (int k0 = 0; k0 < K; k0 += 16) {
        {
            int am = tid >> 2, ak = (tid & 3) << 2;
            float4 av = *(const float4*)(A + (m0 + am) * K + k0 + ak);
            As[ak + 0][am] = av.x; As[ak + 1][am] = av.y;
            As[ak + 2][am] = av.z; As[ak + 3][am] = av.w;
            int bk = tid >> 4, bn = (tid & 15) << 2;
            *(float4*)&Bs[bk][bn] = *(const float4*)(Bm + (k0 + bk) * N + n0 + bn);
        }
        __syncthreads();
        #pragma unroll
        for (int k = 0; k < 16; k++) {
            float4 a4 = *(float4*)&As[k][ty << 2];
            float4 b4 = *(float4*)&Bs[k][tx << 2];
            float ar[4] = {a4.x, a4.y, a4.z, a4.w};
            float br[4] = {b4.x, b4.y, b4.z, b4.w};
            #pragma unroll
            for (int i = 0; i < 4; i++)
                #pragma unroll
                for (int j = 0; j < 4; j++)
                    acc[i][j] = fmaf(ar[i], br[j], acc[i][j]);
        }
        __syncthreads();
    }
    // epilogue: bias + split q/k/v + head split -> [h][s][d]
    #pragma unroll
    for (int i = 0; i < 4; i++) {
        int m = m0 + (ty << 2) + i;
        #pragma unroll
        for (int j = 0; j < 4; j++) {
            int n = n0 + (tx << 2) + j;
            float v = acc[i][j] + bias[n];
            int part = n >> 10;        // 0:q 1:k 2:v
            int r = n & 1023;
            int h = r >> 6, dd = r & 63;
            float* dst = (part == 0) ? g_q : (part == 1) ? g_k : g_v;
            dst[(h * SEQ + m) * DH + dd] = v;
        }
    }
}

__global__ __launch_bounds__(256) void proj_kernel(const float* __restrict__ Bm,
                                                   const float* __restrict__ bias,
                                                   float* __restrict__ out) {
    __shared__ float As[16][68];
    __shared__ float Bs[16][64];
    const int K = HID, N = HID;
    const int n0 = blockIdx.x * 64, m0 = blockIdx.y * 64;
    const int tid = threadIdx.x;
    const int tx = tid & 15, ty = tid >> 4;
    float acc[4][4] = {};
    for (int k0 = 0; k0 < K; k0 += 16) {
        {
            int am = tid >> 2, ak = (tid & 3) << 2;
            float4 av = *(const float4*)(g_ctx + (m0 + am) * K + k0 + ak);
            As[ak + 0][am] = av.x; As[ak + 1][am] = av.y;
            As[ak + 2][am] = av.z; As[ak + 3][am] = av.w;
            int bk = tid >> 4, bn = (tid & 15) << 2;
            *(float4*)&Bs[bk][bn] = *(const float4*)(Bm + (k0 + bk) * N + n0 + bn);
        }
        __syncthreads();
        #pragma unroll
        for (int k = 0; k < 16; k++) {
            float4 a4 = *(float4*)&As[k][ty << 2];
            float4 b4 = *(float4*)&Bs[k][tx << 2];
            float ar[4] = {a4.x, a4.y, a4.z, a4.w};
            float br[4] = {b4.x, b4.y, b4.z, b4.w};
            #pragma unroll
            for (int i = 0; i < 4; i++)
                #pragma unroll
                for (int j = 0; j < 4; j++)
                    acc[i][j] = fmaf(ar[i], br[j], acc[i][j]);
        }
        __syncthreads();
    }
    #pragma unroll
    for (int i = 0; i < 4; i++) {
        int m = m0 + (ty << 2) + i;
        #pragma unroll
        for (int j = 0; j < 4; j++) {
            int n = n0 + (tx << 2) + j;
            out[m * N + n] = acc[i][j] + bias[n];
        }
    }
}

// ---------------------------------------------------------------------------
// Flash attention with fused Transformer-XL relative bias.
//   scores[i][j] = (q_i.k_j + q_i.E[S-1-(i-j)]) * 0.125   for j<=i
//                = -10000                                  for j> i (exp -> 0)
// Block = 64 queries x one head, streams 64-key tiles 0..i0/64.
// ---------------------------------------------------------------------------

#define SM_QS 0                       // [64][68]  Qs[d][i]
#define SM_KS (SM_QS + 64 * 68)       // [64][68]  Ks[d][j]
#define SM_VS (SM_KS + 64 * 68)       // [64][64]  Vs[j][d]
#define SM_ES (SM_VS + 64 * 64)       // [64][129] Es[d][t]  (t = band index, 127 used)
#define SM_PS (SM_ES + 64 * 129)      // [64][68]  Ps[j][i]
#define SM_FLOATS (SM_PS + 64 * 68)   // 25408 floats = 101632 bytes

__global__ __launch_bounds__(256, 2) void attn_kernel(const float* __restrict__ E) {
    extern __shared__ float sm[];
    float* Qs = sm + SM_QS;
    float* Ks = sm + SM_KS;
    float* Vs = sm + SM_VS;
    float* Es = sm + SM_ES;
    float* Ps = sm + SM_PS;

    const int h  = blockIdx.y;
    const int i0 = (gridDim.x - 1 - blockIdx.x) * 64;  // big tiles launch first
    const int tid = threadIdx.x;
    const int tx = tid & 15, ty = tid >> 4;

    // Load Q tile (transposed into Qs[d][i])
    {
        const float* q = g_q + (h * SEQ + i0) * DH;
        #pragma unroll
        for (int it = 0; it < 4; it++) {
            int idx = tid + it * 256;             // 1024 float4 slots
            int row = idx >> 4, c4 = (idx & 15) << 2;
            float4 v = *(const float4*)(q + row * DH + c4);
            Qs[(c4 + 0) * 68 + row] = v.x;
            Qs[(c4 + 1) * 68 + row] = v.y;
            Qs[(c4 + 2) * 68 + row] = v.z;
            Qs[(c4 + 3) * 68 + row] = v.w;
        }
    }

    float m_i[4], l_i[4], acc[4][4];
    #pragma unroll
    for (int i = 0; i < 4; i++) {
        m_i[i] = -INFINITY; l_i[i] = 0.f;
        #pragma unroll
        for (int j = 0; j < 4; j++) acc[i][j] = 0.f;
    }

    const int ntiles = (i0 >> 6) + 1;
    for (int jt = 0; jt < ntiles; jt++) {
        const int j0 = jt << 6;
        __syncthreads();   // previous PV done; also covers initial Q store

        // K tile (transposed), V tile (natural)
        {
            const float* kp = g_k + (h * SEQ + j0) * DH;
            const float* vp = g_v + (h * SEQ + j0) * DH;
            #pragma unroll
            for (int it = 0; it < 4; it++) {
                int idx = tid + it * 256;
                int row = idx >> 4, c4 = (idx & 15) << 2;
                float4 kv = *(const float4*)(kp + row * DH + c4);
                Ks[(c4 + 0) * 68 + row] = kv.x;
                Ks[(c4 + 1) * 68 + row] = kv.y;
                Ks[(c4 + 2) * 68 + row] = kv.z;
                Ks[(c4 + 3) * 68 + row] = kv.w;
                *(float4*)&Vs[row * 64 + c4] = *(const float4*)(vp + row * DH + c4);
            }
        }
        // E band: rows m = mb + t, t in [0,127); stored transposed Es[d][t]
        {
            const int mb = SEQ - 64 - i0 + j0;
            const float* ep = E + h * SEQ * DH;
            for (int idx = tid; idx < 127 * 16; idx += 256) {
                int t = idx >> 4, c4 = (idx & 15) << 2;
                int gm = mb + t;
                float4 v = make_float4(0.f, 0.f, 0.f, 0.f);
                if (gm >= 0 && gm < SEQ) v = *(const float4*)(ep + gm * DH + c4);
                Es[(c4 + 0) * 129 + t] = v.x;
                Es[(c4 + 1) * 129 + t] = v.y;
                Es[(c4 + 2) * 129 + t] = v.z;
                Es[(c4 + 3) * 129 + t] = v.w;
            }
        }
        __syncthreads();

        // ---- scores: q.k ----
        float sc[4][4] = {};
        #pragma unroll 4
        for (int d = 0; d < 64; d++) {
            float4 q4 = *(float4*)&Qs[d * 68 + (ty << 2)];
            float4 k4 = *(float4*)&Ks[d * 68 + (tx << 2)];
            float qr[4] = {q4.x, q4.y, q4.z, q4.w};
            float kr[4] = {k4.x, k4.y, k4.z, k4.w};
            #pragma unroll
            for (int i = 0; i < 4; i++)
                #pragma unroll
                for (int j = 0; j < 4; j++)
                    sc[i][j] = fmaf(qr[i], kr[j], sc[i][j]);
        }
        // ---- scores: + q.E_band ----
        {
            const int tbase = 63 + (tx << 2) - (ty << 2);   // in [3,123]
            #pragma unroll 4
            for (int d = 0; d < 64; d++) {
                float4 q4 = *(float4*)&Qs[d * 68 + (ty << 2)];
                float qr[4] = {q4.x, q4.y, q4.z, q4.w};
                float e7[7];
                #pragma unroll
                for (int u = 0; u < 7; u++) e7[u] = Es[d * 129 + tbase - 3 + u];
                #pragma unroll
                for (int i = 0; i < 4; i++)
                    #pragma unroll
                    for (int j = 0; j < 4; j++)
                        sc[i][j] = fmaf(qr[i], e7[j - i + 3], sc[i][j]);
            }
        }

        // ---- mask + online softmax (row group = 16 lanes sharing ty) ----
        #pragma unroll
        for (int i = 0; i < 4; i++) {
            int gi = i0 + (ty << 2) + i;
            float rmax = -INFINITY;
            #pragma unroll
            for (int j = 0; j < 4; j++) {
                int gj = j0 + (tx << 2) + j;
                float s = (gj <= gi) ? sc[i][j] * 0.125f : -10000.0f;
                sc[i][j] = s;
                rmax = fmaxf(rmax, s);
            }
            #pragma unroll
            for (int off = 1; off < 16; off <<= 1)
                rmax = fmaxf(rmax, __shfl_xor_sync(0xffffffffu, rmax, off));
            float newm = fmaxf(m_i[i], rmax);
            float alpha = __expf(m_i[i] - newm);
            float psum = 0.f;
            #pragma unroll
            for (int j = 0; j < 4; j++) {
                float p = __expf(sc[i][j] - newm);
                sc[i][j] = p;
                psum += p;
            }
            #pragma unroll
            for (int off = 1; off < 16; off <<= 1)
                psum += __shfl_xor_sync(0xffffffffu, psum, off);
            l_i[i] = l_i[i] * alpha + psum;
            m_i[i] = newm;
            #pragma unroll
            for (int j = 0; j < 4; j++) acc[i][j] *= alpha;
        }

        // ---- store P transposed Ps[j][i] ----
        #pragma unroll
        for (int i = 0; i < 4; i++)
            #pragma unroll
            for (int j = 0; j < 4; j++)
                Ps[((tx << 2) + j) * 68 + (ty << 2) + i] = sc[i][j];
        __syncthreads();

        // ---- O += P @ V ----
        #pragma unroll 4
        for (int j = 0; j < 64; j++) {
            float4 p4 = *(float4*)&Ps[j * 68 + (ty << 2)];
            float4 v4 = *(float4*)&Vs[j * 64 + (tx << 2)];
            float pr[4] = {p4.x, p4.y, p4.z, p4.w};
            float vr[4] = {v4.x, v4.y, v4.z, v4.w};
            #pragma unroll
            for (int i = 0; i < 4; i++)
                #pragma unroll
                for (int c = 0; c < 4; c++)
                    acc[i][c] = fmaf(pr[i], vr[c], acc[i][c]);
        }
    }

    // ---- write ctx, head-merged ----
    #pragma unroll
    for (int i = 0; i < 4; i++) {
        float inv = 1.0f / l_i[i];
        int row = i0 + (ty << 2) + i;
        #pragma unroll
        for (int c = 0; c < 4; c++)
            g_ctx[row * HID + h * DH + (tx << 2) + c] = acc[i][c] * inv;
    }
}

// ---------------------------------------------------------------------------

extern "C" void kernel_launch(void* const* d_in, const int* in_sizes, int n_in,
                              void* d_out, int out_size) {
    const float* x   = (const float*)d_in[0];
    const float* caw = (const float*)d_in[1];
    const float* cab = (const float*)d_in[2];
    const float* cpw = (const float*)d_in[3];
    const float* cpb = (const float*)d_in[4];
    const float* E   = (const float*)d_in[5];
    float* out = (float*)d_out;

    const int smem_attn = SM_FLOATS * (int)sizeof(float);  // 101632 B
    cudaFuncSetAttribute(attn_kernel, cudaFuncAttributeMaxDynamicSharedMemorySize,
                         smem_attn);

    qkv_kernel<<<dim3(N_QKV / 64, SEQ / 64), 256>>>(x, caw, cab);
    attn_kernel<<<dim3(SEQ / 64, NH), 256, smem_attn>>>(E);
    proj_kernel<<<dim3(HID / 64, SEQ / 64), 256>>>(cpw, cpb, out);
}

// round 2
// speedup vs baseline: 1.3358x; 1.3358x over previous
#include <cuda_runtime.h>
#include <math.h>

#define SEQ   2048
#define HID   1024
#define NH    16
#define DH    64
#define N_QKV 3072

__device__ __align__(16) float g_q[NH * SEQ * DH];
__device__ __align__(16) float g_k[NH * SEQ * DH];
__device__ __align__(16) float g_v[NH * SEQ * DH];
__device__ __align__(16) float g_ctx[SEQ * HID];

// ---------------------------------------------------------------------------
// SGEMM: 128x128 block tile, BK=16, 256 threads, 8x8 microtile.
// A-transpose stores use lane-row-major mapping (conflict-free STS).
// ---------------------------------------------------------------------------

__global__ __launch_bounds__(256) void qkv_kernel(const float* __restrict__ A,
                                                  const float* __restrict__ Bm,
                                                  const float* __restrict__ bias) {
    __shared__ float As[16][132];
    __shared__ float Bs[16][128];
    const int K = HID, N = N_QKV;
    const int n0 = blockIdx.x * 128, m0 = blockIdx.y * 128;
    const int tid = threadIdx.x;
    const int tx = tid & 15, ty = tid >> 4;
    float acc[8][8] = {};

    for (int k0 = 0; k0 < K; k0 += 16) {
        #pragma unroll
        for (int it = 0; it < 2; it++) {
            int idx = tid + it * 256;
            int am = idx & 127, ak = (idx >> 7) << 2;
            float4 a = *(const float4*)(A + (m0 + am) * K + k0 + ak);
            As[ak + 0][am] = a.x; As[ak + 1][am] = a.y;
            As[ak + 2][am] = a.z; As[ak + 3][am] = a.w;
            int bk = idx >> 5, bn = (idx & 31) << 2;
            *(float4*)&Bs[bk][bn] = *(const float4*)(Bm + (k0 + bk) * N + n0 + bn);
        }
        __syncthreads();
        #pragma unroll
        for (int k = 0; k < 16; k++) {
            float4 a0 = *(float4*)&As[k][ty * 8];
            float4 a1 = *(float4*)&As[k][ty * 8 + 4];
            float4 b0 = *(float4*)&Bs[k][tx * 4];
            float4 b1 = *(float4*)&Bs[k][64 + tx * 4];
            float ar[8] = {a0.x, a0.y, a0.z, a0.w, a1.x, a1.y, a1.z, a1.w};
            float br[8] = {b0.x, b0.y, b0.z, b0.w, b1.x, b1.y, b1.z, b1.w};
            #pragma unroll
            for (int i = 0; i < 8; i++)
                #pragma unroll
                for (int j = 0; j < 8; j++)
                    acc[i][j] = fmaf(ar[i], br[j], acc[i][j]);
        }
        __syncthreads();
    }
    #pragma unroll
    for (int i = 0; i < 8; i++) {
        int m = m0 + ty * 8 + i;
        #pragma unroll
        for (int jh = 0; jh < 2; jh++) {
            int n = n0 + jh * 64 + tx * 4;          // 4 contiguous cols, same head
            int part = n >> 10;
            int r = n & 1023;
            int hh = r >> 6, dd = r & 63;
            float* dst = (part == 0) ? g_q : (part == 1) ? g_k : g_v;
            float4 v;
            v.x = acc[i][jh * 4 + 0] + bias[n + 0];
            v.y = acc[i][jh * 4 + 1] + bias[n + 1];
            v.z = acc[i][jh * 4 + 2] + bias[n + 2];
            v.w = acc[i][jh * 4 + 3] + bias[n + 3];
            *(float4*)&dst[(hh * SEQ + m) * DH + dd] = v;
        }
    }
}

__global__ __launch_bounds__(256) void proj_kernel(const float* __restrict__ Bm,
                                                   const float* __restrict__ bias,
                                                   float* __restrict__ out) {
    __shared__ float As[16][132];
    __shared__ float Bs[16][128];
    const int K = HID, N = HID;
    const int n0 = blockIdx.x * 128, m0 = blockIdx.y * 128;
    const int tid = threadIdx.x;
    const int tx = tid & 15, ty = tid >> 4;
    float acc[8][8] = {};

    for (int k0 = 0; k0 < K; k0 += 16) {
        #pragma unroll
        for (int it = 0; it < 2; it++) {
            int idx = tid + it * 256;
            int am = idx & 127, ak = (idx >> 7) << 2;
            float4 a = *(const float4*)(g_ctx + (m0 + am) * K + k0 + ak);
            As[ak + 0][am] = a.x; As[ak + 1][am] = a.y;
            As[ak + 2][am] = a.z; As[ak + 3][am] = a.w;
            int bk = idx >> 5, bn = (idx & 31) << 2;
            *(float4*)&Bs[bk][bn] = *(const float4*)(Bm + (k0 + bk) * N + n0 + bn);
        }
        __syncthreads();
        #pragma unroll
        for (int k = 0; k < 16; k++) {
            float4 a0 = *(float4*)&As[k][ty * 8];
            float4 a1 = *(float4*)&As[k][ty * 8 + 4];
            float4 b0 = *(float4*)&Bs[k][tx * 4];
            float4 b1 = *(float4*)&Bs[k][64 + tx * 4];
            float ar[8] = {a0.x, a0.y, a0.z, a0.w, a1.x, a1.y, a1.z, a1.w};
            float br[8] = {b0.x, b0.y, b0.z, b0.w, b1.x, b1.y, b1.z, b1.w};
            #pragma unroll
            for (int i = 0; i < 8; i++)
                #pragma unroll
                for (int j = 0; j < 8; j++)
                    acc[i][j] = fmaf(ar[i], br[j], acc[i][j]);
        }
        __syncthreads();
    }
    #pragma unroll
    for (int i = 0; i < 8; i++) {
        int m = m0 + ty * 8 + i;
        #pragma unroll
        for (int jh = 0; jh < 2; jh++) {
            int n = n0 + jh * 64 + tx * 4;
            float4 v;
            v.x = acc[i][jh * 4 + 0] + bias[n + 0];
            v.y = acc[i][jh * 4 + 1] + bias[n + 1];
            v.z = acc[i][jh * 4 + 2] + bias[n + 2];
            v.w = acc[i][jh * 4 + 3] + bias[n + 3];
            *(float4*)&out[m * N + n] = v;
        }
    }
}

// ---------------------------------------------------------------------------
// Flash attention, fused relative bias.
//   s[i][j] = q_i . (k_j + E[S-1-(i-j)])   (then *0.125, causal mask)
// Block: 128 queries x 1 head. Key tiles of 64. 256 threads, 8x4 microtile.
// E band (192 cols) stored transposed Es[d][t]; per-thread window is
// float4-aligned (base-7 ≡ 0 mod 4), so 3 LDS.128 per d.
// ---------------------------------------------------------------------------

#define QS_ST 132
#define KS_ST 68
#define VS_ST 68
#define ES_ST 192
#define PS_ST 68
#define SM_FLOATS (64*QS_ST + 64*KS_ST + 64*VS_ST + 64*ES_ST + 128*PS_ST)

__global__ __launch_bounds__(256, 1) void attn_kernel(const float* __restrict__ E) {
    extern __shared__ float sm[];
    float* Qs = sm;                      // [64][132]  Qs[d][li]
    float* Ks = Qs + 64 * QS_ST;         // [64][68]   Ks[d][lj]
    float* Vs = Ks + 64 * KS_ST;         // [64][68]   Vs[lj][d]
    float* Es = Vs + 64 * VS_ST;         // [64][192]  Es[d][t]
    float* Ps = Es + 64 * ES_ST;         // [128][68]  Ps[li][lj]

    const int bid = blockIdx.x;
    const int h = bid & 15;
    const int i0 = (15 - (bid >> 4)) * 128;   // heaviest tiles first
    const int tid = threadIdx.x;
    const int tx = tid & 15, ty = tid >> 4;
    const int ebase = 120 - 8 * ty + 4 * tx;  // window start (≡0 mod 4)

    // Q tile transposed (lane-row mapping: conflict-free STS)
    {
        const float* qp = g_q + (h * SEQ + i0) * DH;
        #pragma unroll
        for (int it = 0; it < 8; it++) {
            int idx = tid + it * 256;
            int row = idx & 127, c4 = (idx >> 7) << 2;
            float4 v = *(const float4*)(qp + row * DH + c4);
            Qs[(c4 + 0) * QS_ST + row] = v.x;
            Qs[(c4 + 1) * QS_ST + row] = v.y;
            Qs[(c4 + 2) * QS_ST + row] = v.z;
            Qs[(c4 + 3) * QS_ST + row] = v.w;
        }
    }

    float m_i[8], l_i[8], acc[8][4];
    #pragma unroll
    for (int r = 0; r < 8; r++) {
        m_i[r] = -1e30f; l_i[r] = 0.f;
        #pragma unroll
        for (int c = 0; c < 4; c++) acc[r][c] = 0.f;
    }

    const int ntiles = (i0 >> 6) + 2;
    for (int jt = 0; jt < ntiles; jt++) {
        const int j0 = jt << 6;
        __syncthreads();   // prev PV reads done / Q store visible

        // K transposed, V natural
        {
            const float* kp = g_k + (h * SEQ + j0) * DH;
            const float* vp = g_v + (h * SEQ + j0) * DH;
            #pragma unroll
            for (int it = 0; it < 4; it++) {
                int idx = tid + it * 256;
                int row = idx & 63, c4 = (idx >> 6) << 2;
                float4 kv = *(const float4*)(kp + row * DH + c4);
                Ks[(c4 + 0) * KS_ST + row] = kv.x;
                Ks[(c4 + 1) * KS_ST + row] = kv.y;
                Ks[(c4 + 2) * KS_ST + row] = kv.z;
                Ks[(c4 + 3) * KS_ST + row] = kv.w;
                int vrow = idx >> 4, vc4 = (idx & 15) << 2;
                *(float4*)&Vs[vrow * VS_ST + vc4] = *(const float4*)(vp + vrow * DH + vc4);
            }
        }
        // E band transposed: t = 127 - li + lj  (t in [0,192))
        {
            const int mb = SEQ - 128 - i0 + j0;
            const float* ep = E + h * SEQ * DH;
            #pragma unroll
            for (int it = 0; it < 12; it++) {
                int idx = tid + it * 256;
                int t = idx % 192;
                int c4 = (idx / 192) << 2;
                int gm = mb + t;
                float4 v = make_float4(0.f, 0.f, 0.f, 0.f);
                if (gm >= 0 && gm < SEQ) v = *(const float4*)(ep + gm * DH + c4);
                Es[(c4 + 0) * ES_ST + t] = v.x;
                Es[(c4 + 1) * ES_ST + t] = v.y;
                Es[(c4 + 2) * ES_ST + t] = v.z;
                Es[(c4 + 3) * ES_ST + t] = v.w;
            }
        }
        __syncthreads();

        // ---- scores: q . (k + e_band), single d pass ----
        float sc[8][4] = {};
        #pragma unroll 4
        for (int d = 0; d < 64; d++) {
            float4 a0 = *(float4*)&Qs[d * QS_ST + ty * 8];
            float4 a1 = *(float4*)&Qs[d * QS_ST + ty * 8 + 4];
            float4 kv = *(float4*)&Ks[d * KS_ST + tx * 4];
            float4 e0 = *(float4*)&Es[d * ES_ST + ebase];
            float4 e1 = *(float4*)&Es[d * ES_ST + ebase + 4];
            float4 e2 = *(float4*)&Es[d * ES_ST + ebase + 8];
            float qr[8] = {a0.x, a0.y, a0.z, a0.w, a1.x, a1.y, a1.z, a1.w};
            float kr[4] = {kv.x, kv.y, kv.z, kv.w};
            float er[12] = {e0.x, e0.y, e0.z, e0.w, e1.x, e1.y, e1.z, e1.w,
                            e2.x, e2.y, e2.z, e2.w};
            #pragma unroll
            for (int r = 0; r < 8; r++)
                #pragma unroll
                for (int c = 0; c < 4; c++)
                    sc[r][c] = fmaf(qr[r], kr[c] + er[c - r + 7], sc[r][c]);
        }

        // ---- mask + online softmax (16 lanes share a row group) ----
        #pragma unroll
        for (int r = 0; r < 8; r++) {
            int gi = i0 + ty * 8 + r;
            float rmax = -1e30f;
            #pragma unroll
            for (int c = 0; c < 4; c++) {
                int gj = j0 + tx * 4 + c;
                float s = (gj <= gi) ? sc[r][c] * 0.125f : -10000.0f;
                sc[r][c] = s;
                rmax = fmaxf(rmax, s);
            }
            #pragma unroll
            for (int off = 1; off < 16; off <<= 1)
                rmax = fmaxf(rmax, __shfl_xor_sync(0xffffffffu, rmax, off));
            float newm = fmaxf(m_i[r], rmax);
            float alpha = __expf(m_i[r] - newm);
            m_i[r] = newm;
            float ps = 0.f;
            #pragma unroll
            for (int c = 0; c < 4; c++) {
                float p = __expf(sc[r][c] - newm);
                sc[r][c] = p;
                ps += p;
            }
            #pragma unroll
            for (int off = 1; off < 16; off <<= 1)
                ps += __shfl_xor_sync(0xffffffffu, ps, off);
            l_i[r] = l_i[r] * alpha + ps;
            #pragma unroll
            for (int c = 0; c < 4; c++) acc[r][c] *= alpha;
        }

        // ---- P to smem (row-major, float4, conflict-free) ----
        #pragma unroll
        for (int r = 0; r < 8; r++)
            *(float4*)&Ps[(ty * 8 + r) * PS_ST + tx * 4] =
                make_float4(sc[r][0], sc[r][1], sc[r][2], sc[r][3]);
        __syncthreads();

        // ---- O += P @ V (chunks of 4 keys) ----
        #pragma unroll 4
        for (int jc = 0; jc < 16; jc++) {
            float4 v0 = *(float4*)&Vs[(jc * 4 + 0) * VS_ST + tx * 4];
            float4 v1 = *(float4*)&Vs[(jc * 4 + 1) * VS_ST + tx * 4];
            float4 v2 = *(float4*)&Vs[(jc * 4 + 2) * VS_ST + tx * 4];
            float4 v3 = *(float4*)&Vs[(jc * 4 + 3) * VS_ST + tx * 4];
            #pragma unroll
            for (int r = 0; r < 8; r++) {
                float4 p = *(float4*)&Ps[(ty * 8 + r) * PS_ST + jc * 4];
                acc[r][0] = fmaf(p.x, v0.x, acc[r][0]);
                acc[r][0] = fmaf(p.y, v1.x, acc[r][0]);
                acc[r][0] = fmaf(p.z, v2.x, acc[r][0]);
                acc[r][0] = fmaf(p.w, v3.x, acc[r][0]);
                acc[r][1] = fmaf(p.x, v0.y, acc[r][1]);
                acc[r][1] = fmaf(p.y, v1.y, acc[r][1]);
                acc[r][1] = fmaf(p.z, v2.y, acc[r][1]);
                acc[r][1] = fmaf(p.w, v3.y, acc[r][1]);
                acc[r][2] = fmaf(p.x, v0.z, acc[r][2]);
                acc[r][2] = fmaf(p.y, v1.z, acc[r][2]);
                acc[r][2] = fmaf(p.z, v2.z, acc[r][2]);
                acc[r][2] = fmaf(p.w, v3.z, acc[r][2]);
                acc[r][3] = fmaf(p.x, v0.w, acc[r][3]);
                acc[r][3] = fmaf(p.y, v1.w, acc[r][3]);
                acc[r][3] = fmaf(p.z, v2.w, acc[r][3]);
                acc[r][3] = fmaf(p.w, v3.w, acc[r][3]);
            }
        }
    }

    // ---- write ctx head-merged ----
    #pragma unroll
    for (int r = 0; r < 8; r++) {
        float inv = 1.0f / l_i[r];
        int row = i0 + ty * 8 + r;
        float4 o = make_float4(acc[r][0] * inv, acc[r][1] * inv,
                               acc[r][2] * inv, acc[r][3] * inv);
        *(float4*)&g_ctx[row * HID + h * DH + tx * 4] = o;
    }
}

// ---------------------------------------------------------------------------

extern "C" void kernel_launch(void* const* d_in, const int* in_sizes, int n_in,
                              void* d_out, int out_size) {
    const float* x   = (const float*)d_in[0];
    const float* caw = (const float*)d_in[1];
    const float* cab = (const float*)d_in[2];
    const float* cpw = (const float*)d_in[3];
    const float* cpb = (const float*)d_in[4];
    const float* E   = (const float*)d_in[5];
    float* out = (float*)d_out;

    const int smem_attn = SM_FLOATS * (int)sizeof(float);  // 152576 B
    cudaFuncSetAttribute(attn_kernel, cudaFuncAttributeMaxDynamicSharedMemorySize,
                         smem_attn);

    qkv_kernel<<<dim3(N_QKV / 128, SEQ / 128), 256>>>(x, caw, cab);
    attn_kernel<<<dim3(256), 256, smem_attn>>>(E);
    proj_kernel<<<dim3(HID / 128, SEQ / 128), 256>>>(cpw, cpb, out);
}

// round 5
// speedup vs baseline: 1.8161x; 1.3596x over previous
#include <cuda_runtime.h>
#include <cuda_bf16.h>
#include <math.h>
#include <stdint.h>

#define SEQ   2048
#define HID   1024
#define NH    16
#define DH    64
#define N_QKV 3072

// fp32 scratch
__device__ __align__(16) float g_q[NH * SEQ * DH];
__device__ __align__(16) float g_k[NH * SEQ * DH];
__device__ __align__(16) float g_v[NH * SEQ * DH];
__device__ __align__(16) float g_ctx[SEQ * HID];

// bf16-split operands (K-major rows)
__device__ __align__(16) __nv_bfloat16 g_xh[SEQ * HID];
__device__ __align__(16) __nv_bfloat16 g_xl[SEQ * HID];
__device__ __align__(16) __nv_bfloat16 g_wah[N_QKV * HID];   // [N][K]
__device__ __align__(16) __nv_bfloat16 g_wal[N_QKV * HID];
__device__ __align__(16) __nv_bfloat16 g_wph[HID * HID];     // [N][K]
__device__ __align__(16) __nv_bfloat16 g_wpl[HID * HID];
__device__ __align__(16) __nv_bfloat16 g_cth[SEQ * HID];
__device__ __align__(16) __nv_bfloat16 g_ctl[SEQ * HID];

// ---------------------------------------------------------------------------
// warp-mma helpers (compute_80-level PTX -> HMMA on sm_103)
// ---------------------------------------------------------------------------
__device__ __forceinline__ uint32_t smem_u32(const void* p) {
    uint32_t a;
    asm("{ .reg .u64 t; cvta.to.shared.u64 t, %1; cvt.u32.u64 %0, t; }"
        : "=r"(a) : "l"(p));
    return a;
}
__device__ __forceinline__ void ldm_x4(uint32_t* r, uint32_t addr) {
    asm volatile("ldmatrix.sync.aligned.m8n8.x4.shared.b16 {%0,%1,%2,%3}, [%4];"
                 : "=r"(r[0]), "=r"(r[1]), "=r"(r[2]), "=r"(r[3]) : "r"(addr));
}
__device__ __forceinline__ void ldm_x2(uint32_t* r, uint32_t addr) {
    asm volatile("ldmatrix.sync.aligned.m8n8.x2.shared.b16 {%0,%1}, [%2];"
                 : "=r"(r[0]), "=r"(r[1]) : "r"(addr));
}
__device__ __forceinline__ void mma_bf16(float* d, const uint32_t* a, const uint32_t* b) {
    asm volatile("mma.sync.aligned.m16n8k16.row.col.f32.bf16.bf16.f32 "
                 "{%0,%1,%2,%3}, {%4,%5,%6,%7}, {%8,%9}, {%0,%1,%2,%3};"
                 : "+f"(d[0]), "+f"(d[1]), "+f"(d[2]), "+f"(d[3])
                 : "r"(a[0]), "r"(a[1]), "r"(a[2]), "r"(a[3]), "r"(b[0]), "r"(b[1]));
}
__device__ __forceinline__ uint32_t swz128(uint32_t off) {
    return off ^ ((off >> 3) & 0x70);
}

// ---------------------------------------------------------------------------
// fp32 -> bf16 hi/lo split (elementwise)
// ---------------------------------------------------------------------------
__global__ __launch_bounds__(256) void split_kernel(const float* __restrict__ s,
                                                    __nv_bfloat16* __restrict__ h,
                                                    __nv_bfloat16* __restrict__ l,
                                                    int n) {
    int i = (blockIdx.x * 256 + threadIdx.x) * 4;
    if (i >= n) return;
    float4 v = *(const float4*)(s + i);
    float vv[4] = {v.x, v.y, v.z, v.w};
    __nv_bfloat16 hh[4], ll[4];
    #pragma unroll
    for (int c = 0; c < 4; c++) {
        hh[c] = __float2bfloat16(vv[c]);
        ll[c] = __float2bfloat16(vv[c] - __bfloat162float(hh[c]));
    }
    *(__nv_bfloat162*)(h + i)     = __nv_bfloat162(hh[0], hh[1]);
    *(__nv_bfloat162*)(h + i + 2) = __nv_bfloat162(hh[2], hh[3]);
    *(__nv_bfloat162*)(l + i)     = __nv_bfloat162(ll[0], ll[1]);
    *(__nv_bfloat162*)(l + i + 2) = __nv_bfloat162(ll[2], ll[3]);
}

// fp32 [K,N] -> bf16 hi/lo [N,K]
__global__ __launch_bounds__(256) void transpose_split_kernel(const float* __restrict__ s,
                                                              __nv_bfloat16* __restrict__ h,
                                                              __nv_bfloat16* __restrict__ l,
                                                              int K, int N) {
    __shared__ float t[32][33];
    int tx = threadIdx.x, ty = threadIdx.y;
    #pragma unroll
    for (int r = 0; r < 4; r++) {
        int k = blockIdx.y * 32 + ty + r * 8;
        int n = blockIdx.x * 32 + tx;
        t[ty + r * 8][tx] = s[k * N + n];
    }
    __syncthreads();
    #pragma unroll
    for (int r = 0; r < 4; r++) {
        int n = blockIdx.x * 32 + ty + r * 8;
        int k = blockIdx.y * 32 + tx;
        float a = t[tx][ty + r * 8];
        __nv_bfloat16 hh = __float2bfloat16(a);
        h[n * K + k] = hh;
        l[n * K + k] = __float2bfloat16(a - __bfloat162float(hh));
    }
}

// ---------------------------------------------------------------------------
// Tensor-core GEMM via mma.sync bf16, 3-term split, fp32 acc.
// D[128x128] per CTA = A[128xK] . B[NxK]^T.  K = 1024 (16 slabs of 64).
// 8 warps: 2(m) x 4(n), warp tile 64x32, fragments m16n8k16.
// EPI 0: qkv scatter (+bias -> g_q/g_k/g_v);  EPI 1: +bias -> outp.
// ---------------------------------------------------------------------------
#define SM_AH 0
#define SM_AL 16384
#define SM_BH 32768
#define SM_BL 49152
#define SM_GEMM 65536

template<int EPI>
__global__ __launch_bounds__(256) void gemm_tc(const __nv_bfloat16* __restrict__ Ahg,
                                               const __nv_bfloat16* __restrict__ Alg,
                                               const __nv_bfloat16* __restrict__ Bhg,
                                               const __nv_bfloat16* __restrict__ Blg,
                                               const float* __restrict__ bias,
                                               float* __restrict__ outp,
                                               int Ncols) {
    extern __shared__ char smc[];
    const uint32_t sb = smem_u32(smc);
    const int tid = threadIdx.x;
    const int wid = tid >> 5;
    const int lane = tid & 31;
    const int m0 = blockIdx.y * 128;
    const int n0 = blockIdx.x * 128;
    const int K = 1024;
    const int wm = wid & 1;         // 0..1
    const int wn = wid >> 1;        // 0..3

    float acc[4][4][4] = {};

    // ldmatrix per-lane address offsets (within a [128 x 64bf16] swizzled tile)
    // A x4: quad q = lane>>3: row += (q&1)*8, k += (q>>1)*8
    const int aq = lane >> 3, ar = lane & 7;
    const int a_row_off = (aq & 1) * 8 + ar;
    const int a_k_off   = (aq >> 1) * 8;
    // B x2: q = (lane>>3)&1: row = n + r, k += q*8
    const int bq = (lane >> 3) & 1, br = lane & 7;

    for (int slab = 0; slab < 16; slab++) {
        const int k0 = slab * 64;
        if (slab) __syncthreads();
        // load AH/AL/BH/BL tiles [128 rows x 64 bf16] swizzled
        #pragma unroll
        for (int it = 0; it < 4; it++) {
            int idx = tid + it * 256;
            int row = idx >> 3, ch = idx & 7;
            uint32_t soff = swz128((uint32_t)(row * 128 + ch * 16));
            *(uint4*)(smc + SM_AH + soff) = *(const uint4*)(Ahg + (m0 + row) * K + k0 + ch * 8);
            *(uint4*)(smc + SM_AL + soff) = *(const uint4*)(Alg + (m0 + row) * K + k0 + ch * 8);
            *(uint4*)(smc + SM_BH + soff) = *(const uint4*)(Bhg + (n0 + row) * K + k0 + ch * 8);
            *(uint4*)(smc + SM_BL + soff) = *(const uint4*)(Blg + (n0 + row) * K + k0 + ch * 8);
        }
        __syncthreads();

        #pragma unroll
        for (int ks = 0; ks < 4; ks++) {
            const int kk = ks * 16;
            uint32_t ah[4][4], al[4][4], bh[4][2], bl[4][2];
            #pragma unroll
            for (int mf = 0; mf < 4; mf++) {
                int row = wm * 64 + mf * 16 + a_row_off;
                uint32_t off = swz128((uint32_t)(row * 128 + (kk + a_k_off) * 2));
                ldm_x4(ah[mf], sb + SM_AH + off);
                ldm_x4(al[mf], sb + SM_AL + off);
            }
            #pragma unroll
            for (int nf = 0; nf < 4; nf++) {
                int row = wn * 32 + nf * 8 + br;
                uint32_t off = swz128((uint32_t)(row * 128 + (kk + bq * 8) * 2));
                ldm_x2(bh[nf], sb + SM_BH + off);
                ldm_x2(bl[nf], sb + SM_BL + off);
            }
            #pragma unroll
            for (int mf = 0; mf < 4; mf++)
                #pragma unroll
                for (int nf = 0; nf < 4; nf++) {
                    mma_bf16(acc[mf][nf], ah[mf], bh[nf]);
                    mma_bf16(acc[mf][nf], ah[mf], bl[nf]);
                    mma_bf16(acc[mf][nf], al[mf], bh[nf]);
                }
        }
    }

    // ---- epilogue ----
    const int r0 = lane >> 2;
    const int c0 = (lane & 3) * 2;
    #pragma unroll
    for (int mf = 0; mf < 4; mf++) {
        #pragma unroll
        for (int nf = 0; nf < 4; nf++) {
            int n = n0 + wn * 32 + nf * 8 + c0;
            int m1 = m0 + wm * 64 + mf * 16 + r0;
            float b0 = bias[n], b1 = bias[n + 1];
            float2 v0 = make_float2(acc[mf][nf][0] + b0, acc[mf][nf][1] + b1);
            float2 v1 = make_float2(acc[mf][nf][2] + b0, acc[mf][nf][3] + b1);
            if (EPI == 0) {
                int part = n >> 10;
                int rr = n & 1023;
                int hh = rr >> 6, dd = rr & 63;
                float* dst = (part == 0) ? g_q : (part == 1) ? g_k : g_v;
                *(float2*)(dst + (hh * SEQ + m1) * DH + dd) = v0;
                *(float2*)(dst + (hh * SEQ + m1 + 8) * DH + dd) = v1;
            } else {
                *(float2*)(outp + m1 * Ncols + n) = v0;
                *(float2*)(outp + (m1 + 8) * Ncols + n) = v1;
            }
        }
    }
}

// ---------------------------------------------------------------------------
// Flash attention with fused relative bias (round-2 version, fp32 FFMA).
// ---------------------------------------------------------------------------
#define QS_ST 132
#define KS_ST 68
#define VS_ST 68
#define ES_ST 192
#define PS_ST 68
#define SM_FLOATS (64*QS_ST + 64*KS_ST + 64*VS_ST + 64*ES_ST + 128*PS_ST)

__global__ __launch_bounds__(256, 1) void attn_kernel(const float* __restrict__ E) {
    extern __shared__ float sm[];
    float* Qs = sm;
    float* Ks = Qs + 64 * QS_ST;
    float* Vs = Ks + 64 * KS_ST;
    float* Es = Vs + 64 * VS_ST;
    float* Ps = Es + 64 * ES_ST;

    const int bid = blockIdx.x;
    const int h = bid & 15;
    const int i0 = (15 - (bid >> 4)) * 128;
    const int tid = threadIdx.x;
    const int tx = tid & 15, ty = tid >> 4;
    const int ebase = 120 - 8 * ty + 4 * tx;

    {
        const float* qp = g_q + (h * SEQ + i0) * DH;
        #pragma unroll
        for (int it = 0; it < 8; it++) {
            int idx = tid + it * 256;
            int row = idx & 127, c4 = (idx >> 7) << 2;
            float4 v = *(const float4*)(qp + row * DH + c4);
            Qs[(c4 + 0) * QS_ST + row] = v.x;
            Qs[(c4 + 1) * QS_ST + row] = v.y;
            Qs[(c4 + 2) * QS_ST + row] = v.z;
            Qs[(c4 + 3) * QS_ST + row] = v.w;
        }
    }

    float m_i[8], l_i[8], acc[8][4];
    #pragma unroll
    for (int r = 0; r < 8; r++) {
        m_i[r] = -1e30f; l_i[r] = 0.f;
        #pragma unroll
        for (int c = 0; c < 4; c++) acc[r][c] = 0.f;
    }

    const int ntiles = (i0 >> 6) + 2;
    for (int jt = 0; jt < ntiles; jt++) {
        const int j0 = jt << 6;
        __syncthreads();

        {
            const float* kp = g_k + (h * SEQ + j0) * DH;
            const float* vp = g_v + (h * SEQ + j0) * DH;
            #pragma unroll
            for (int it = 0; it < 4; it++) {
                int idx = tid + it * 256;
                int row = idx & 63, c4 = (idx >> 6) << 2;
                float4 kv = *(const float4*)(kp + row * DH + c4);
                Ks[(c4 + 0) * KS_ST + row] = kv.x;
                Ks[(c4 + 1) * KS_ST + row] = kv.y;
                Ks[(c4 + 2) * KS_ST + row] = kv.z;
                Ks[(c4 + 3) * KS_ST + row] = kv.w;
                int vrow = idx >> 4, vc4 = (idx & 15) << 2;
                *(float4*)&Vs[vrow * VS_ST + vc4] = *(const float4*)(vp + vrow * DH + vc4);
            }
        }
        {
            const int mb = SEQ - 128 - i0 + j0;
            const float* ep = E + h * SEQ * DH;
            #pragma unroll
            for (int it = 0; it < 12; it++) {
                int idx = tid + it * 256;
                int t = idx % 192;
                int c4 = (idx / 192) << 2;
                int gm = mb + t;
                float4 v = make_float4(0.f, 0.f, 0.f, 0.f);
                if (gm >= 0 && gm < SEQ) v = *(const float4*)(ep + gm * DH + c4);
                Es[(c4 + 0) * ES_ST + t] = v.x;
                Es[(c4 + 1) * ES_ST + t] = v.y;
                Es[(c4 + 2) * ES_ST + t] = v.z;
                Es[(c4 + 3) * ES_ST + t] = v.w;
            }
        }
        __syncthreads();

        float sc[8][4] = {};
        #pragma unroll 4
        for (int d = 0; d < 64; d++) {
            float4 a0 = *(float4*)&Qs[d * QS_ST + ty * 8];
            float4 a1 = *(float4*)&Qs[d * QS_ST + ty * 8 + 4];
            float4 kv = *(float4*)&Ks[d * KS_ST + tx * 4];
            float4 e0 = *(float4*)&Es[d * ES_ST + ebase];
            float4 e1 = *(float4*)&Es[d * ES_ST + ebase + 4];
            float4 e2 = *(float4*)&Es[d * ES_ST + ebase + 8];
            float qr[8] = {a0.x, a0.y, a0.z, a0.w, a1.x, a1.y, a1.z, a1.w};
            float kr[4] = {kv.x, kv.y, kv.z, kv.w};
            float er[12] = {e0.x, e0.y, e0.z, e0.w, e1.x, e1.y, e1.z, e1.w,
                            e2.x, e2.y, e2.z, e2.w};
            #pragma unroll
            for (int r = 0; r < 8; r++)
                #pragma unroll
                for (int c = 0; c < 4; c++)
                    sc[r][c] = fmaf(qr[r], kr[c] + er[c - r + 7], sc[r][c]);
        }

        #pragma unroll
        for (int r = 0; r < 8; r++) {
            int gi = i0 + ty * 8 + r;
            float rmax = -1e30f;
            #pragma unroll
            for (int c = 0; c < 4; c++) {
                int gj = j0 + tx * 4 + c;
                float s = (gj <= gi) ? sc[r][c] * 0.125f : -10000.0f;
                sc[r][c] = s;
                rmax = fmaxf(rmax, s);
            }
            #pragma unroll
            for (int off = 1; off < 16; off <<= 1)
                rmax = fmaxf(rmax, __shfl_xor_sync(0xffffffffu, rmax, off));
            float newm = fmaxf(m_i[r], rmax);
            float alpha = __expf(m_i[r] - newm);
            m_i[r] = newm;
            float ps = 0.f;
            #pragma unroll
            for (int c = 0; c < 4; c++) {
                float p = __expf(sc[r][c] - newm);
                sc[r][c] = p;
                ps += p;
            }
            #pragma unroll
            for (int off = 1; off < 16; off <<= 1)
                ps += __shfl_xor_sync(0xffffffffu, ps, off);
            l_i[r] = l_i[r] * alpha + ps;
            #pragma unroll
            for (int c = 0; c < 4; c++) acc[r][c] *= alpha;
        }

        #pragma unroll
        for (int r = 0; r < 8; r++)
            *(float4*)&Ps[(ty * 8 + r) * PS_ST + tx * 4] =
                make_float4(sc[r][0], sc[r][1], sc[r][2], sc[r][3]);
        __syncthreads();

        #pragma unroll 4
        for (int jc = 0; jc < 16; jc++) {
            float4 v0 = *(float4*)&Vs[(jc * 4 + 0) * VS_ST + tx * 4];
            float4 v1 = *(float4*)&Vs[(jc * 4 + 1) * VS_ST + tx * 4];
            float4 v2 = *(float4*)&Vs[(jc * 4 + 2) * VS_ST + tx * 4];
            float4 v3 = *(float4*)&Vs[(jc * 4 + 3) * VS_ST + tx * 4];
            #pragma unroll
            for (int r = 0; r < 8; r++) {
                float4 p = *(float4*)&Ps[(ty * 8 + r) * PS_ST + jc * 4];
                acc[r][0] = fmaf(p.x, v0.x, acc[r][0]);
                acc[r][0] = fmaf(p.y, v1.x, acc[r][0]);
                acc[r][0] = fmaf(p.z, v2.x, acc[r][0]);
                acc[r][0] = fmaf(p.w, v3.x, acc[r][0]);
                acc[r][1] = fmaf(p.x, v0.y, acc[r][1]);
                acc[r][1] = fmaf(p.y, v1.y, acc[r][1]);
                acc[r][1] = fmaf(p.z, v2.y, acc[r][1]);
                acc[r][1] = fmaf(p.w, v3.y, acc[r][1]);
                acc[r][2] = fmaf(p.x, v0.z, acc[r][2]);
                acc[r][2] = fmaf(p.y, v1.z, acc[r][2]);
                acc[r][2] = fmaf(p.z, v2.z, acc[r][2]);
                acc[r][2] = fmaf(p.w, v3.z, acc[r][2]);
                acc[r][3] = fmaf(p.x, v0.w, acc[r][3]);
                acc[r][3] = fmaf(p.y, v1.w, acc[r][3]);
                acc[r][3] = fmaf(p.z, v2.w, acc[r][3]);
                acc[r][3] = fmaf(p.w, v3.w, acc[r][3]);
            }
        }
    }

    #pragma unroll
    for (int r = 0; r < 8; r++) {
        float inv = 1.0f / l_i[r];
        int row = i0 + ty * 8 + r;
        float4 o = make_float4(acc[r][0] * inv, acc[r][1] * inv,
                               acc[r][2] * inv, acc[r][3] * inv);
        *(float4*)&g_ctx[row * HID + h * DH + tx * 4] = o;
    }
}

// ---------------------------------------------------------------------------

extern "C" void kernel_launch(void* const* d_in, const int* in_sizes, int n_in,
                              void* d_out, int out_size) {
    const float* x   = (const float*)d_in[0];
    const float* caw = (const float*)d_in[1];
    const float* cab = (const float*)d_in[2];
    const float* cpw = (const float*)d_in[3];
    const float* cpb = (const float*)d_in[4];
    const float* E   = (const float*)d_in[5];
    float* out = (float*)d_out;

    const int smem_attn = SM_FLOATS * (int)sizeof(float);
    cudaFuncSetAttribute(attn_kernel, cudaFuncAttributeMaxDynamicSharedMemorySize,
                         smem_attn);
    cudaFuncSetAttribute(gemm_tc<0>, cudaFuncAttributeMaxDynamicSharedMemorySize,
                         SM_GEMM);
    cudaFuncSetAttribute(gemm_tc<1>, cudaFuncAttributeMaxDynamicSharedMemorySize,
                         SM_GEMM);

    __nv_bfloat16 *xh, *xl, *wah, *wal, *wph, *wpl, *cth, *ctl;
    cudaGetSymbolAddress((void**)&xh,  g_xh);
    cudaGetSymbolAddress((void**)&xl,  g_xl);
    cudaGetSymbolAddress((void**)&wah, g_wah);
    cudaGetSymbolAddress((void**)&wal, g_wal);
    cudaGetSymbolAddress((void**)&wph, g_wph);
    cudaGetSymbolAddress((void**)&wpl, g_wpl);
    cudaGetSymbolAddress((void**)&cth, g_cth);
    cudaGetSymbolAddress((void**)&ctl, g_ctl);
    float* ctx;
    cudaGetSymbolAddress((void**)&ctx, g_ctx);

    split_kernel<<<(SEQ * HID) / 1024, 256>>>(x, xh, xl, SEQ * HID);
    transpose_split_kernel<<<dim3(N_QKV / 32, HID / 32), dim3(32, 8)>>>(caw, wah, wal, HID, N_QKV);
    transpose_split_kernel<<<dim3(HID / 32, HID / 32), dim3(32, 8)>>>(cpw, wph, wpl, HID, HID);

    gemm_tc<0><<<dim3(N_QKV / 128, SEQ / 128), 256, SM_GEMM>>>(xh, xl, wah, wal,
                                                               cab, nullptr, N_QKV);
    attn_kernel<<<dim3(256), 256, smem_attn>>>(E);

    split_kernel<<<(SEQ * HID) / 1024, 256>>>(ctx, cth, ctl, SEQ * HID);
    gemm_tc<1><<<dim3(HID / 128, SEQ / 128), 256, SM_GEMM>>>(cth, ctl, wph, wpl,
                                                             cpb, out, HID);
}

// round 6
// speedup vs baseline: 2.7850x; 1.5335x over previous
#include <cuda_runtime.h>
#include <cuda_bf16.h>
#include <math.h>
#include <stdint.h>

#define SEQ   2048
#define HID   1024
#define NH    16
#define DH    64
#define N_QKV 3072

// bf16-split scratch
__device__ __align__(16) __nv_bfloat16 g_qh[NH * SEQ * DH];
__device__ __align__(16) __nv_bfloat16 g_ql[NH * SEQ * DH];
__device__ __align__(16) __nv_bfloat16 g_kh[NH * SEQ * DH];
__device__ __align__(16) __nv_bfloat16 g_kl[NH * SEQ * DH];
__device__ __align__(16) __nv_bfloat16 g_vth[NH * DH * SEQ];   // [h][d][seq]
__device__ __align__(16) __nv_bfloat16 g_vtl[NH * DH * SEQ];
__device__ __align__(16) __nv_bfloat16 g_eh[NH * SEQ * DH];
__device__ __align__(16) __nv_bfloat16 g_el[NH * SEQ * DH];
__device__ __align__(16) __nv_bfloat16 g_xh[SEQ * HID];
__device__ __align__(16) __nv_bfloat16 g_xl[SEQ * HID];
__device__ __align__(16) __nv_bfloat16 g_wah[N_QKV * HID];     // [N][K]
__device__ __align__(16) __nv_bfloat16 g_wal[N_QKV * HID];
__device__ __align__(16) __nv_bfloat16 g_wph[HID * HID];
__device__ __align__(16) __nv_bfloat16 g_wpl[HID * HID];
__device__ __align__(16) __nv_bfloat16 g_cth[SEQ * HID];
__device__ __align__(16) __nv_bfloat16 g_ctl[SEQ * HID];

// ---------------------------------------------------------------------------
// helpers
// ---------------------------------------------------------------------------
__device__ __forceinline__ uint32_t smem_u32(const void* p) {
    uint32_t a;
    asm("{ .reg .u64 t; cvta.to.shared.u64 t, %1; cvt.u32.u64 %0, t; }"
        : "=r"(a) : "l"(p));
    return a;
}
__device__ __forceinline__ void ldm_x4(uint32_t* r, uint32_t addr) {
    asm volatile("ldmatrix.sync.aligned.m8n8.x4.shared.b16 {%0,%1,%2,%3}, [%4];"
                 : "=r"(r[0]), "=r"(r[1]), "=r"(r[2]), "=r"(r[3]) : "r"(addr));
}
__device__ __forceinline__ void ldm_x2(uint32_t* r, uint32_t addr) {
    asm volatile("ldmatrix.sync.aligned.m8n8.x2.shared.b16 {%0,%1}, [%2];"
                 : "=r"(r[0]), "=r"(r[1]) : "r"(addr));
}
__device__ __forceinline__ void mma_bf16(float* d, const uint32_t* a, const uint32_t* b) {
    asm volatile("mma.sync.aligned.m16n8k16.row.col.f32.bf16.bf16.f32 "
                 "{%0,%1,%2,%3}, {%4,%5,%6,%7}, {%8,%9}, {%0,%1,%2,%3};"
                 : "+f"(d[0]), "+f"(d[1]), "+f"(d[2]), "+f"(d[3])
                 : "r"(a[0]), "r"(a[1]), "r"(a[2]), "r"(a[3]), "r"(b[0]), "r"(b[1]));
}
__device__ __forceinline__ uint32_t swz128(uint32_t off) {
    return off ^ ((off >> 3) & 0x70);
}
__device__ __forceinline__ void cpa16(uint32_t s, const void* g) {
    asm volatile("cp.async.ca.shared.global [%0], [%1], 16;" :: "r"(s), "l"(g));
}
__device__ __forceinline__ void cpa_commit() {
    asm volatile("cp.async.commit_group;" ::: "memory");
}
template<int N>
__device__ __forceinline__ void cpa_wait() {
    asm volatile("cp.async.wait_group %0;" :: "n"(N) : "memory");
}

// ---------------------------------------------------------------------------
// fp32 -> bf16 hi/lo split
// ---------------------------------------------------------------------------
__global__ __launch_bounds__(256) void split_kernel(const float* __restrict__ s,
                                                    __nv_bfloat16* __restrict__ h,
                                                    __nv_bfloat16* __restrict__ l,
                                                    int n) {
    int i = (blockIdx.x * 256 + threadIdx.x) * 4;
    if (i >= n) return;
    float4 v = *(const float4*)(s + i);
    float vv[4] = {v.x, v.y, v.z, v.w};
    __nv_bfloat16 hh[4], ll[4];
    #pragma unroll
    for (int c = 0; c < 4; c++) {
        hh[c] = __float2bfloat16(vv[c]);
        ll[c] = __float2bfloat16(vv[c] - __bfloat162float(hh[c]));
    }
    *(__nv_bfloat162*)(h + i)     = __nv_bfloat162(hh[0], hh[1]);
    *(__nv_bfloat162*)(h + i + 2) = __nv_bfloat162(hh[2], hh[3]);
    *(__nv_bfloat162*)(l + i)     = __nv_bfloat162(ll[0], ll[1]);
    *(__nv_bfloat162*)(l + i + 2) = __nv_bfloat162(ll[2], ll[3]);
}

// fp32 [K,N] -> bf16 hi/lo [N,K]
__global__ __launch_bounds__(256) void transpose_split_kernel(const float* __restrict__ s,
                                                              __nv_bfloat16* __restrict__ h,
                                                              __nv_bfloat16* __restrict__ l,
                                                              int K, int N) {
    __shared__ float t[32][33];
    int tx = threadIdx.x, ty = threadIdx.y;
    #pragma unroll
    for (int r = 0; r < 4; r++) {
        int k = blockIdx.y * 32 + ty + r * 8;
        int n = blockIdx.x * 32 + tx;
        t[ty + r * 8][tx] = s[k * N + n];
    }
    __syncthreads();
    #pragma unroll
    for (int r = 0; r < 4; r++) {
        int n = blockIdx.x * 32 + ty + r * 8;
        int k = blockIdx.y * 32 + tx;
        float a = t[tx][ty + r * 8];
        __nv_bfloat16 hh = __float2bfloat16(a);
        h[n * K + k] = hh;
        l[n * K + k] = __float2bfloat16(a - __bfloat162float(hh));
    }
}

// ---------------------------------------------------------------------------
// cp.async double-buffered tensor-core GEMM, bf16 3-term split, fp32 acc.
// D[128x128] per CTA; K=1024 (16 slabs of 64). 8 warps 2(m)x4(n).
// EPI 0: qkv epilogue -> bf16 splits of Q, K, V-transposed.
// EPI 1: +bias -> fp32 outp.
// ---------------------------------------------------------------------------
#define SM_AH 0
#define SM_AL 16384
#define SM_BH 32768
#define SM_BL 49152
#define SM_STAGE 65536
#define SM_GEMM (2 * SM_STAGE)

template<int EPI>
__global__ __launch_bounds__(256) void gemm_tc(const __nv_bfloat16* __restrict__ Ahg,
                                               const __nv_bfloat16* __restrict__ Alg,
                                               const __nv_bfloat16* __restrict__ Bhg,
                                               const __nv_bfloat16* __restrict__ Blg,
                                               const float* __restrict__ bias,
                                               float* __restrict__ outp,
                                               int Ncols) {
    extern __shared__ char smc[];
    const uint32_t sb = smem_u32(smc);
    const int tid = threadIdx.x;
    const int wid = tid >> 5;
    const int lane = tid & 31;
    const int m0 = blockIdx.y * 128;
    const int n0 = blockIdx.x * 128;
    const int K = 1024;
    const int wm = wid & 1;
    const int wn = wid >> 1;

    float acc[4][4][4] = {};

    const int aq = lane >> 3, ar = lane & 7;
    const int a_row_off = (aq & 1) * 8 + ar;
    const int a_k_off   = (aq >> 1) * 8;
    const int bq = (lane >> 3) & 1, br = lane & 7;

    // prefetch slab 0
    {
        #pragma unroll
        for (int it2 = 0; it2 < 4; it2++) {
            int idx = tid + it2 * 256;
            int row = idx >> 3, ch = idx & 7;
            uint32_t soff = swz128((uint32_t)(row * 128 + ch * 16));
            cpa16(sb + SM_AH + soff, Ahg + (m0 + row) * K + ch * 8);
            cpa16(sb + SM_AL + soff, Alg + (m0 + row) * K + ch * 8);
            cpa16(sb + SM_BH + soff, Bhg + (n0 + row) * K + ch * 8);
            cpa16(sb + SM_BL + soff, Blg + (n0 + row) * K + ch * 8);
        }
        cpa_commit();
    }

    for (int slab = 0; slab < 16; slab++) {
        if (slab < 15) {
            const int k0 = (slab + 1) * 64;
            const uint32_t sbase = sb + ((slab + 1) & 1) * SM_STAGE;
            #pragma unroll
            for (int it2 = 0; it2 < 4; it2++) {
                int idx = tid + it2 * 256;
                int row = idx >> 3, ch = idx & 7;
                uint32_t soff = swz128((uint32_t)(row * 128 + ch * 16));
                cpa16(sbase + SM_AH + soff, Ahg + (m0 + row) * K + k0 + ch * 8);
                cpa16(sbase + SM_AL + soff, Alg + (m0 + row) * K + k0 + ch * 8);
                cpa16(sbase + SM_BH + soff, Bhg + (n0 + row) * K + k0 + ch * 8);
                cpa16(sbase + SM_BL + soff, Blg + (n0 + row) * K + k0 + ch * 8);
            }
            cpa_commit();
            cpa_wait<1>();
        } else {
            cpa_wait<0>();
        }
        __syncthreads();

        const uint32_t st = sb + (slab & 1) * SM_STAGE;
        #pragma unroll
        for (int ks = 0; ks < 4; ks++) {
            const int kk = ks * 16;
            uint32_t ah[4][4], al4[4][4], bh[4][2], bl[4][2];
            #pragma unroll
            for (int mf = 0; mf < 4; mf++) {
                int row = wm * 64 + mf * 16 + a_row_off;
                uint32_t off = swz128((uint32_t)(row * 128 + (kk + a_k_off) * 2));
                ldm_x4(ah[mf], st + SM_AH + off);
                ldm_x4(al4[mf], st + SM_AL + off);
            }
            #pragma unroll
            for (int nf = 0; nf < 4; nf++) {
                int row = wn * 32 + nf * 8 + br;
                uint32_t off = swz128((uint32_t)(row * 128 + (kk + bq * 8) * 2));
                ldm_x2(bh[nf], st + SM_BH + off);
                ldm_x2(bl[nf], st + SM_BL + off);
            }
            #pragma unroll
            for (int mf = 0; mf < 4; mf++)
                #pragma unroll
                for (int nf = 0; nf < 4; nf++) {
                    mma_bf16(acc[mf][nf], ah[mf], bh[nf]);
                    mma_bf16(acc[mf][nf], ah[mf], bl[nf]);
                    mma_bf16(acc[mf][nf], al4[mf], bh[nf]);
                }
        }
        __syncthreads();
    }

    // ---- epilogue ----
    const int r0 = lane >> 2;
    const int c0 = (lane & 3) * 2;
    #pragma unroll
    for (int mf = 0; mf < 4; mf++) {
        #pragma unroll
        for (int nf = 0; nf < 4; nf++) {
            int n = n0 + wn * 32 + nf * 8 + c0;
            int m1 = m0 + wm * 64 + mf * 16 + r0;
            float b0 = bias[n], b1 = bias[n + 1];
            float v00 = acc[mf][nf][0] + b0, v01 = acc[mf][nf][1] + b1;
            float v10 = acc[mf][nf][2] + b0, v11 = acc[mf][nf][3] + b1;
            if (EPI == 0) {
                int part = n >> 10;
                int rr = n & 1023;
                int hh = rr >> 6, dd = rr & 63;
                __nv_bfloat16 h00 = __float2bfloat16(v00);
                __nv_bfloat16 h01 = __float2bfloat16(v01);
                __nv_bfloat16 h10 = __float2bfloat16(v10);
                __nv_bfloat16 h11 = __float2bfloat16(v11);
                __nv_bfloat16 l00 = __float2bfloat16(v00 - __bfloat162float(h00));
                __nv_bfloat16 l01 = __float2bfloat16(v01 - __bfloat162float(h01));
                __nv_bfloat16 l10 = __float2bfloat16(v10 - __bfloat162float(h10));
                __nv_bfloat16 l11 = __float2bfloat16(v11 - __bfloat162float(h11));
                if (part == 2) {
                    // V transposed: [h][d][seq]
                    long base0 = (long)(hh * DH + dd) * SEQ;
                    long base1 = (long)(hh * DH + dd + 1) * SEQ;
                    g_vth[base0 + m1]     = h00;  g_vtl[base0 + m1]     = l00;
                    g_vth[base1 + m1]     = h01;  g_vtl[base1 + m1]     = l01;
                    g_vth[base0 + m1 + 8] = h10;  g_vtl[base0 + m1 + 8] = l10;
                    g_vth[base1 + m1 + 8] = h11;  g_vtl[base1 + m1 + 8] = l11;
                } else {
                    __nv_bfloat16* dh = (part == 0) ? g_qh : g_kh;
                    __nv_bfloat16* dl = (part == 0) ? g_ql : g_kl;
                    long a0 = (long)(hh * SEQ + m1) * DH + dd;
                    long a1 = (long)(hh * SEQ + m1 + 8) * DH + dd;
                    *(__nv_bfloat162*)(dh + a0) = __nv_bfloat162(h00, h01);
                    *(__nv_bfloat162*)(dl + a0) = __nv_bfloat162(l00, l01);
                    *(__nv_bfloat162*)(dh + a1) = __nv_bfloat162(h10, h11);
                    *(__nv_bfloat162*)(dl + a1) = __nv_bfloat162(l10, l11);
                }
            } else {
                *(float2*)(outp + (long)m1 * Ncols + n) = make_float2(v00, v01);
                *(float2*)(outp + (long)(m1 + 8) * Ncols + n) = make_float2(v10, v11);
            }
        }
    }
}

// ---------------------------------------------------------------------------
// Tensor-core flash attention with fused relative bias.
// CTA = (head, 64-query tile). B operand = [K tile (64) ; E band (128)] ->
// S[64x192] = Q @ B^T in one mma pass; gather s[r][c] = S[r][c] + S[r][127-r+c].
// P.V via mma with V pre-transposed. All matmuls 3-term bf16 split.
// ---------------------------------------------------------------------------
#define AT_QH 0
#define AT_QL 8192
#define AT_BH 16384
#define AT_BL 40960
#define AT_VH 65536
#define AT_VL 73728
#define AT_S  81920                 // 64 x 196 fp32
#define AT_PH 132096
#define AT_PL 140288
#define AT_ALPHA 148480
#define AT_LS 148736
#define AT_SMEM 148992

__global__ __launch_bounds__(256, 1) void attn_tc() {
    extern __shared__ char smc[];
    const uint32_t sb = smem_u32(smc);
    float* S = (float*)(smc + AT_S);
    float* alpha_s = (float*)(smc + AT_ALPHA);
    float* l_s = (float*)(smc + AT_LS);

    const int tid = threadIdx.x;
    const int w = tid >> 5, lane = tid & 31;
    const int bid = blockIdx.x;
    const int it = 31 - (bid >> 4);       // big tiles first
    const int h = bid & 15;
    const int i0 = it * 64;
    const int tx = tid & 15, ty = tid >> 4;

    const int aq = lane >> 3, ar = lane & 7;
    const int a_row_off = (aq & 1) * 8 + ar;
    const int a_k_off   = (aq >> 1) * 8;
    const int bq = (lane >> 3) & 1, br = lane & 7;
    const int r0 = lane >> 2, c0 = (lane & 3) * 2;

    // load Q tile (64 rows x 128B), swizzled
    #pragma unroll
    for (int i2 = 0; i2 < 2; i2++) {
        int idx = tid + i2 * 256;
        int row = idx >> 3, ch = idx & 7;
        uint32_t soff = swz128((uint32_t)(row * 128 + ch * 16));
        long src = (long)(h * SEQ + i0 + row) * DH + ch * 8;
        *(uint4*)(smc + AT_QH + soff) = *(const uint4*)(g_qh + src);
        *(uint4*)(smc + AT_QL + soff) = *(const uint4*)(g_ql + src);
    }

    float m_i[4], l_i[4];
    #pragma unroll
    for (int i = 0; i < 4; i++) { m_i[i] = -1e30f; l_i[i] = 0.f; }
    float accO[4][4] = {};

    const int ntiles = it + 1;
    for (int jt = 0; jt < ntiles; jt++) {
        const int j0 = jt * 64;
        const int mb = 1984 - i0 + j0;
        __syncthreads();

        // B tile: rows 0-63 = K keys, rows 64-191 = E band
        #pragma unroll
        for (int i2 = 0; i2 < 6; i2++) {
            int idx = tid + i2 * 256;
            int row = idx >> 3, ch = idx & 7;
            uint32_t soff = swz128((uint32_t)(row * 128 + ch * 16));
            uint4 vh = make_uint4(0, 0, 0, 0), vl = make_uint4(0, 0, 0, 0);
            if (row < 64) {
                long src = (long)(h * SEQ + j0 + row) * DH + ch * 8;
                vh = *(const uint4*)(g_kh + src);
                vl = *(const uint4*)(g_kl + src);
            } else {
                int m = mb + row - 64;
                if (m < SEQ) {
                    long src = (long)(h * SEQ + m) * DH + ch * 8;
                    vh = *(const uint4*)(g_eh + src);
                    vl = *(const uint4*)(g_el + src);
                }
            }
            *(uint4*)(smc + AT_BH + soff) = vh;
            *(uint4*)(smc + AT_BL + soff) = vl;
        }
        // Vt tile (64 d-rows x 64 keys)
        #pragma unroll
        for (int i2 = 0; i2 < 2; i2++) {
            int idx = tid + i2 * 256;
            int row = idx >> 3, ch = idx & 7;
            uint32_t soff = swz128((uint32_t)(row * 128 + ch * 16));
            long src = (long)(h * DH + row) * SEQ + j0 + ch * 8;
            *(uint4*)(smc + AT_VH + soff) = *(const uint4*)(g_vth + src);
            *(uint4*)(smc + AT_VL + soff) = *(const uint4*)(g_vtl + src);
        }
        __syncthreads();

        // ---- scores MMA: S[64x192], warp w covers cols [w*24, w*24+24) ----
        float sacc[4][3][4] = {};
        #pragma unroll
        for (int ks = 0; ks < 4; ks++) {
            const int kk = ks * 16;
            uint32_t ah[4][4], al4[4][4], bh[3][2], bl[3][2];
            #pragma unroll
            for (int mf = 0; mf < 4; mf++) {
                int row = mf * 16 + a_row_off;
                uint32_t off = swz128((uint32_t)(row * 128 + (kk + a_k_off) * 2));
                ldm_x4(ah[mf], sb + AT_QH + off);
                ldm_x4(al4[mf], sb + AT_QL + off);
            }
            #pragma unroll
            for (int nf = 0; nf < 3; nf++) {
                int row = w * 24 + nf * 8 + br;
                uint32_t off = swz128((uint32_t)(row * 128 + (kk + bq * 8) * 2));
                ldm_x2(bh[nf], sb + AT_BH + off);
                ldm_x2(bl[nf], sb + AT_BL + off);
            }
            #pragma unroll
            for (int mf = 0; mf < 4; mf++)
                #pragma unroll
                for (int nf = 0; nf < 3; nf++) {
                    mma_bf16(sacc[mf][nf], ah[mf], bh[nf]);
                    mma_bf16(sacc[mf][nf], ah[mf], bl[nf]);
                    mma_bf16(sacc[mf][nf], al4[mf], bh[nf]);
                }
        }
        #pragma unroll
        for (int mf = 0; mf < 4; mf++)
            #pragma unroll
            for (int nf = 0; nf < 3; nf++) {
                int cc = w * 24 + nf * 8 + c0;
                *(float2*)&S[(mf * 16 + r0) * 196 + cc] =
                    make_float2(sacc[mf][nf][0], sacc[mf][nf][1]);
                *(float2*)&S[(mf * 16 + r0 + 8) * 196 + cc] =
                    make_float2(sacc[mf][nf][2], sacc[mf][nf][3]);
            }
        __syncthreads();

        // ---- softmax (thread (tx,ty): rows ty*4+i, cols tx*4+c) ----
        #pragma unroll
        for (int i = 0; i < 4; i++) {
            int r = ty * 4 + i;
            int gi = i0 + r;
            float4 s1 = *(float4*)&S[r * 196 + tx * 4];
            int b2 = r * 196 + 127 - r + tx * 4;
            float sv[4];
            sv[0] = s1.x + S[b2];     sv[1] = s1.y + S[b2 + 1];
            sv[2] = s1.z + S[b2 + 2]; sv[3] = s1.w + S[b2 + 3];
            float rmax = -1e30f;
            #pragma unroll
            for (int c = 0; c < 4; c++) {
                int gj = j0 + tx * 4 + c;
                float s = (gj <= gi) ? sv[c] * 0.125f : -10000.0f;
                sv[c] = s;
                rmax = fmaxf(rmax, s);
            }
            #pragma unroll
            for (int off = 1; off < 16; off <<= 1)
                rmax = fmaxf(rmax, __shfl_xor_sync(0xffffffffu, rmax, off));
            float newm = fmaxf(m_i[i], rmax);
            float alpha = __expf(m_i[i] - newm);
            m_i[i] = newm;
            float ps = 0.f;
            #pragma unroll
            for (int c = 0; c < 4; c++) {
                sv[c] = __expf(sv[c] - newm);
                ps += sv[c];
            }
            #pragma unroll
            for (int off = 1; off < 16; off <<= 1)
                ps += __shfl_xor_sync(0xffffffffu, ps, off);
            l_i[i] = l_i[i] * alpha + ps;
            if (tx == 0) alpha_s[r] = alpha;
            // write P (bf16 hi/lo), swizzled row-major [64 x 64]
            __nv_bfloat16 ph[4], pl[4];
            #pragma unroll
            for (int c = 0; c < 4; c++) {
                ph[c] = __float2bfloat16(sv[c]);
                pl[c] = __float2bfloat16(sv[c] - __bfloat162float(ph[c]));
            }
            uint32_t poff = swz128((uint32_t)(r * 128 + tx * 8));
            *(__nv_bfloat162*)(smc + AT_PH + poff)     = __nv_bfloat162(ph[0], ph[1]);
            *(__nv_bfloat162*)(smc + AT_PH + poff + 4) = __nv_bfloat162(ph[2], ph[3]);
            *(__nv_bfloat162*)(smc + AT_PL + poff)     = __nv_bfloat162(pl[0], pl[1]);
            *(__nv_bfloat162*)(smc + AT_PL + poff + 4) = __nv_bfloat162(pl[2], pl[3]);
        }
        __syncthreads();

        // ---- PV MMA: warp w -> m-range (w&3)*16, n-range (w>>2)*32 ----
        float a0 = alpha_s[(w & 3) * 16 + r0];
        float a1 = alpha_s[(w & 3) * 16 + r0 + 8];
        #pragma unroll
        for (int nf = 0; nf < 4; nf++) {
            accO[nf][0] *= a0; accO[nf][1] *= a0;
            accO[nf][2] *= a1; accO[nf][3] *= a1;
        }
        #pragma unroll
        for (int ks = 0; ks < 4; ks++) {
            const int kk = ks * 16;
            uint32_t ph[4], pl4[4], vh[4][2], vl[4][2];
            int arow = (w & 3) * 16 + a_row_off;
            uint32_t aoff = swz128((uint32_t)(arow * 128 + (kk + a_k_off) * 2));
            ldm_x4(ph, sb + AT_PH + aoff);
            ldm_x4(pl4, sb + AT_PL + aoff);
            #pragma unroll
            for (int nf = 0; nf < 4; nf++) {
                int row = (w >> 2) * 32 + nf * 8 + br;
                uint32_t off = swz128((uint32_t)(row * 128 + (kk + bq * 8) * 2));
                ldm_x2(vh[nf], sb + AT_VH + off);
                ldm_x2(vl[nf], sb + AT_VL + off);
            }
            #pragma unroll
            for (int nf = 0; nf < 4; nf++) {
                mma_bf16(accO[nf], ph, vh[nf]);
                mma_bf16(accO[nf], ph, vl[nf]);
                mma_bf16(accO[nf], pl4, vh[nf]);
            }
        }
    }

    // ---- epilogue: normalize, split to bf16, write ctx ----
    if (tx == 0) {
        #pragma unroll
        for (int i = 0; i < 4; i++) l_s[ty * 4 + i] = l_i[i];
    }
    __syncthreads();
    {
        int rr0 = (w & 3) * 16 + r0;
        float inv0 = 1.0f / l_s[rr0];
        float inv1 = 1.0f / l_s[rr0 + 8];
        #pragma unroll
        for (int nf = 0; nf < 4; nf++) {
            int c = (w >> 2) * 32 + nf * 8 + c0;
            int col = h * DH + c;
            float o00 = accO[nf][0] * inv0, o01 = accO[nf][1] * inv0;
            float o10 = accO[nf][2] * inv1, o11 = accO[nf][3] * inv1;
            __nv_bfloat16 h00 = __float2bfloat16(o00), h01 = __float2bfloat16(o01);
            __nv_bfloat16 h10 = __float2bfloat16(o10), h11 = __float2bfloat16(o11);
            __nv_bfloat16 l00 = __float2bfloat16(o00 - __bfloat162float(h00));
            __nv_bfloat16 l01 = __float2bfloat16(o01 - __bfloat162float(h01));
            __nv_bfloat16 l10 = __float2bfloat16(o10 - __bfloat162float(h10));
            __nv_bfloat16 l11 = __float2bfloat16(o11 - __bfloat162float(h11));
            long a0 = (long)(i0 + rr0) * HID + col;
            long a1 = (long)(i0 + rr0 + 8) * HID + col;
            *(__nv_bfloat162*)(g_cth + a0) = __nv_bfloat162(h00, h01);
            *(__nv_bfloat162*)(g_ctl + a0) = __nv_bfloat162(l00, l01);
            *(__nv_bfloat162*)(g_cth + a1) = __nv_bfloat162(h10, h11);
            *(__nv_bfloat162*)(g_ctl + a1) = __nv_bfloat162(l10, l11);
        }
    }
}

// ---------------------------------------------------------------------------

extern "C" void kernel_launch(void* const* d_in, const int* in_sizes, int n_in,
                              void* d_out, int out_size) {
    const float* x   = (const float*)d_in[0];
    const float* caw = (const float*)d_in[1];
    const float* cab = (const float*)d_in[2];
    const float* cpw = (const float*)d_in[3];
    const float* cpb = (const float*)d_in[4];
    const float* E   = (const float*)d_in[5];
    float* out = (float*)d_out;

    cudaFuncSetAttribute(gemm_tc<0>, cudaFuncAttributeMaxDynamicSharedMemorySize, SM_GEMM);
    cudaFuncSetAttribute(gemm_tc<1>, cudaFuncAttributeMaxDynamicSharedMemorySize, SM_GEMM);
    cudaFuncSetAttribute(attn_tc, cudaFuncAttributeMaxDynamicSharedMemorySize, AT_SMEM);

    __nv_bfloat16 *xh, *xl, *eh, *el, *wah, *wal, *wph, *wpl, *cth, *ctl;
    cudaGetSymbolAddress((void**)&xh,  g_xh);
    cudaGetSymbolAddress((void**)&xl,  g_xl);
    cudaGetSymbolAddress((void**)&eh,  g_eh);
    cudaGetSymbolAddress((void**)&el,  g_el);
    cudaGetSymbolAddress((void**)&wah, g_wah);
    cudaGetSymbolAddress((void**)&wal, g_wal);
    cudaGetSymbolAddress((void**)&wph, g_wph);
    cudaGetSymbolAddress((void**)&wpl, g_wpl);
    cudaGetSymbolAddress((void**)&cth, g_cth);
    cudaGetSymbolAddress((void**)&ctl, g_ctl);

    split_kernel<<<(SEQ * HID) / 1024, 256>>>(x, xh, xl, SEQ * HID);
    split_kernel<<<(NH * SEQ * DH) / 1024, 256>>>(E, eh, el, NH * SEQ * DH);
    transpose_split_kernel<<<dim3(N_QKV / 32, HID / 32), dim3(32, 8)>>>(caw, wah, wal, HID, N_QKV);
    transpose_split_kernel<<<dim3(HID / 32, HID / 32), dim3(32, 8)>>>(cpw, wph, wpl, HID, HID);

    gemm_tc<0><<<dim3(N_QKV / 128, SEQ / 128), 256, SM_GEMM>>>(xh, xl, wah, wal,
                                                               cab, nullptr, N_QKV);
    attn_tc<<<dim3(NH * 32), 256, AT_SMEM>>>();

    gemm_tc<1><<<dim3(HID / 128, SEQ / 128), 256, SM_GEMM>>>(cth, ctl, wph, wpl,
                                                             cpb, out, HID);
}

// round 8
// speedup vs baseline: 2.9197x; 1.0484x over previous
#include <cuda_runtime.h>
#include <cuda_bf16.h>
#include <math.h>
#include <stdint.h>

#define SEQ   2048
#define HID   1024
#define NH    16
#define DH    64
#define N_QKV 3072

// bf16-split scratch
__device__ __align__(16) __nv_bfloat16 g_qh[NH * SEQ * DH];
__device__ __align__(16) __nv_bfloat16 g_ql[NH * SEQ * DH];
__device__ __align__(16) __nv_bfloat16 g_kh[NH * SEQ * DH];
__device__ __align__(16) __nv_bfloat16 g_kl[NH * SEQ * DH];
__device__ __align__(16) __nv_bfloat16 g_vth[NH * DH * SEQ];   // [h][d][seq]
__device__ __align__(16) __nv_bfloat16 g_vtl[NH * DH * SEQ];
__device__ __align__(16) __nv_bfloat16 g_eh[NH * SEQ * DH];
__device__ __align__(16) __nv_bfloat16 g_el[NH * SEQ * DH];
__device__ __align__(16) __nv_bfloat16 g_xh[SEQ * HID];
__device__ __align__(16) __nv_bfloat16 g_xl[SEQ * HID];
__device__ __align__(16) __nv_bfloat16 g_wah[N_QKV * HID];     // [N][K]
__device__ __align__(16) __nv_bfloat16 g_wal[N_QKV * HID];
__device__ __align__(16) __nv_bfloat16 g_wph[HID * HID];
__device__ __align__(16) __nv_bfloat16 g_wpl[HID * HID];
__device__ __align__(16) __nv_bfloat16 g_cth[SEQ * HID];
__device__ __align__(16) __nv_bfloat16 g_ctl[SEQ * HID];

// ---------------------------------------------------------------------------
// helpers
// ---------------------------------------------------------------------------
__device__ __forceinline__ uint32_t smem_u32(const void* p) {
    uint32_t a;
    asm("{ .reg .u64 t; cvta.to.shared.u64 t, %1; cvt.u32.u64 %0, t; }"
        : "=r"(a) : "l"(p));
    return a;
}
__device__ __forceinline__ void ldm_x4(uint32_t* r, uint32_t addr) {
    asm volatile("ldmatrix.sync.aligned.m8n8.x4.shared.b16 {%0,%1,%2,%3}, [%4];"
                 : "=r"(r[0]), "=r"(r[1]), "=r"(r[2]), "=r"(r[3]) : "r"(addr));
}
__device__ __forceinline__ void ldm_x2(uint32_t* r, uint32_t addr) {
    asm volatile("ldmatrix.sync.aligned.m8n8.x2.shared.b16 {%0,%1}, [%2];"
                 : "=r"(r[0]), "=r"(r[1]) : "r"(addr));
}
__device__ __forceinline__ void mma_bf16(float* d, const uint32_t* a, const uint32_t* b) {
    asm volatile("mma.sync.aligned.m16n8k16.row.col.f32.bf16.bf16.f32 "
                 "{%0,%1,%2,%3}, {%4,%5,%6,%7}, {%8,%9}, {%0,%1,%2,%3};"
                 : "+f"(d[0]), "+f"(d[1]), "+f"(d[2]), "+f"(d[3])
                 : "r"(a[0]), "r"(a[1]), "r"(a[2]), "r"(a[3]), "r"(b[0]), "r"(b[1]));
}
__device__ __forceinline__ uint32_t swz128(uint32_t off) {
    return off ^ ((off >> 3) & 0x70);
}
__device__ __forceinline__ void cpa16(uint32_t s, const void* g) {
    asm volatile("cp.async.ca.shared.global [%0], [%1], 16;" :: "r"(s), "l"(g));
}
__device__ __forceinline__ void cpa16z(uint32_t s, const void* g, int sz) {
    asm volatile("cp.async.ca.shared.global [%0], [%1], 16, %2;"
                 :: "r"(s), "l"(g), "r"(sz));
}
__device__ __forceinline__ void cpa_commit() {
    asm volatile("cp.async.commit_group;" ::: "memory");
}
template<int N>
__device__ __forceinline__ void cpa_wait() {
    asm volatile("cp.async.wait_group %0;" :: "n"(N) : "memory");
}

// ---------------------------------------------------------------------------
// fp32 -> bf16 hi/lo split
// ---------------------------------------------------------------------------
__global__ __launch_bounds__(256) void split_kernel(const float* __restrict__ s,
                                                    __nv_bfloat16* __restrict__ h,
                                                    __nv_bfloat16* __restrict__ l,
                                                    int n) {
    int i = (blockIdx.x * 256 + threadIdx.x) * 4;
    if (i >= n) return;
    float4 v = *(const float4*)(s + i);
    float vv[4] = {v.x, v.y, v.z, v.w};
    __nv_bfloat16 hh[4], ll[4];
    #pragma unroll
    for (int c = 0; c < 4; c++) {
        hh[c] = __float2bfloat16(vv[c]);
        ll[c] = __float2bfloat16(vv[c] - __bfloat162float(hh[c]));
    }
    *(__nv_bfloat162*)(h + i)     = __nv_bfloat162(hh[0], hh[1]);
    *(__nv_bfloat162*)(h + i + 2) = __nv_bfloat162(hh[2], hh[3]);
    *(__nv_bfloat162*)(l + i)     = __nv_bfloat162(ll[0], ll[1]);
    *(__nv_bfloat162*)(l + i + 2) = __nv_bfloat162(ll[2], ll[3]);
}

// fp32 [K,N] -> bf16 hi/lo [N,K]
__global__ __launch_bounds__(256) void transpose_split_kernel(const float* __restrict__ s,
                                                              __nv_bfloat16* __restrict__ h,
                                                              __nv_bfloat16* __restrict__ l,
                                                              int K, int N) {
    __shared__ float t[32][33];
    int tx = threadIdx.x, ty = threadIdx.y;
    #pragma unroll
    for (int r = 0; r < 4; r++) {
        int k = blockIdx.y * 32 + ty + r * 8;
        int n = blockIdx.x * 32 + tx;
        t[ty + r * 8][tx] = s[k * N + n];
    }
    __syncthreads();
    #pragma unroll
    for (int r = 0; r < 4; r++) {
        int n = blockIdx.x * 32 + ty + r * 8;
        int k = blockIdx.y * 32 + tx;
        float a = t[tx][ty + r * 8];
        __nv_bfloat16 hh = __float2bfloat16(a);
        h[n * K + k] = hh;
        l[n * K + k] = __float2bfloat16(a - __bfloat162float(hh));
    }
}

// ---------------------------------------------------------------------------
// cp.async double-buffered tensor-core GEMM (unchanged from round 6).
// ---------------------------------------------------------------------------
#define SM_AH 0
#define SM_AL 16384
#define SM_BH 32768
#define SM_BL 49152
#define SM_STAGE 65536
#define SM_GEMM (2 * SM_STAGE)

template<int EPI>
__global__ __launch_bounds__(256) void gemm_tc(const __nv_bfloat16* __restrict__ Ahg,
                                               const __nv_bfloat16* __restrict__ Alg,
                                               const __nv_bfloat16* __restrict__ Bhg,
                                               const __nv_bfloat16* __restrict__ Blg,
                                               const float* __restrict__ bias,
                                               float* __restrict__ outp,
                                               int Ncols) {
    extern __shared__ char smc[];
    const uint32_t sb = smem_u32(smc);
    const int tid = threadIdx.x;
    const int wid = tid >> 5;
    const int lane = tid & 31;
    const int m0 = blockIdx.y * 128;
    const int n0 = blockIdx.x * 128;
    const int K = 1024;
    const int wm = wid & 1;
    const int wn = wid >> 1;

    float acc[4][4][4] = {};

    const int aq = lane >> 3, ar = lane & 7;
    const int a_row_off = (aq & 1) * 8 + ar;
    const int a_k_off   = (aq >> 1) * 8;
    const int bq = (lane >> 3) & 1, br = lane & 7;

    {
        #pragma unroll
        for (int it2 = 0; it2 < 4; it2++) {
            int idx = tid + it2 * 256;
            int row = idx >> 3, ch = idx & 7;
            uint32_t soff = swz128((uint32_t)(row * 128 + ch * 16));
            cpa16(sb + SM_AH + soff, Ahg + (m0 + row) * K + ch * 8);
            cpa16(sb + SM_AL + soff, Alg + (m0 + row) * K + ch * 8);
            cpa16(sb + SM_BH + soff, Bhg + (n0 + row) * K + ch * 8);
            cpa16(sb + SM_BL + soff, Blg + (n0 + row) * K + ch * 8);
        }
        cpa_commit();
    }

    for (int slab = 0; slab < 16; slab++) {
        if (slab < 15) {
            const int k0 = (slab + 1) * 64;
            const uint32_t sbase = sb + ((slab + 1) & 1) * SM_STAGE;
            #pragma unroll
            for (int it2 = 0; it2 < 4; it2++) {
                int idx = tid + it2 * 256;
                int row = idx >> 3, ch = idx & 7;
                uint32_t soff = swz128((uint32_t)(row * 128 + ch * 16));
                cpa16(sbase + SM_AH + soff, Ahg + (m0 + row) * K + k0 + ch * 8);
                cpa16(sbase + SM_AL + soff, Alg + (m0 + row) * K + k0 + ch * 8);
                cpa16(sbase + SM_BH + soff, Bhg + (n0 + row) * K + k0 + ch * 8);
                cpa16(sbase + SM_BL + soff, Blg + (n0 + row) * K + k0 + ch * 8);
            }
            cpa_commit();
            cpa_wait<1>();
        } else {
            cpa_wait<0>();
        }
        __syncthreads();

        const uint32_t st = sb + (slab & 1) * SM_STAGE;
        #pragma unroll
        for (int ks = 0; ks < 4; ks++) {
            const int kk = ks * 16;
            uint32_t ah[4][4], al4[4][4], bh[4][2], bl[4][2];
            #pragma unroll
            for (int mf = 0; mf < 4; mf++) {
                int row = wm * 64 + mf * 16 + a_row_off;
                uint32_t off = swz128((uint32_t)(row * 128 + (kk + a_k_off) * 2));
                ldm_x4(ah[mf], st + SM_AH + off);
                ldm_x4(al4[mf], st + SM_AL + off);
            }
            #pragma unroll
            for (int nf = 0; nf < 4; nf++) {
                int row = wn * 32 + nf * 8 + br;
                uint32_t off = swz128((uint32_t)(row * 128 + (kk + bq * 8) * 2));
                ldm_x2(bh[nf], st + SM_BH + off);
                ldm_x2(bl[nf], st + SM_BL + off);
            }
            #pragma unroll
            for (int mf = 0; mf < 4; mf++)
                #pragma unroll
                for (int nf = 0; nf < 4; nf++) {
                    mma_bf16(acc[mf][nf], ah[mf], bh[nf]);
                    mma_bf16(acc[mf][nf], ah[mf], bl[nf]);
                    mma_bf16(acc[mf][nf], al4[mf], bh[nf]);
                }
        }
        __syncthreads();
    }

    const int r0 = lane >> 2;
    const int c0 = (lane & 3) * 2;
    #pragma unroll
    for (int mf = 0; mf < 4; mf++) {
        #pragma unroll
        for (int nf = 0; nf < 4; nf++) {
            int n = n0 + wn * 32 + nf * 8 + c0;
            int m1 = m0 + wm * 64 + mf * 16 + r0;
            float b0 = bias[n], b1 = bias[n + 1];
            float v00 = acc[mf][nf][0] + b0, v01 = acc[mf][nf][1] + b1;
            float v10 = acc[mf][nf][2] + b0, v11 = acc[mf][nf][3] + b1;
            if (EPI == 0) {
                int part = n >> 10;
                int rr = n & 1023;
                int hh = rr >> 6, dd = rr & 63;
                __nv_bfloat16 h00 = __float2bfloat16(v00);
                __nv_bfloat16 h01 = __float2bfloat16(v01);
                __nv_bfloat16 h10 = __float2bfloat16(v10);
                __nv_bfloat16 h11 = __float2bfloat16(v11);
                __nv_bfloat16 l00 = __float2bfloat16(v00 - __bfloat162float(h00));
                __nv_bfloat16 l01 = __float2bfloat16(v01 - __bfloat162float(h01));
                __nv_bfloat16 l10 = __float2bfloat16(v10 - __bfloat162float(h10));
                __nv_bfloat16 l11 = __float2bfloat16(v11 - __bfloat162float(h11));
                if (part == 2) {
                    long base0 = (long)(hh * DH + dd) * SEQ;
                    long base1 = (long)(hh * DH + dd + 1) * SEQ;
                    g_vth[base0 + m1]     = h00;  g_vtl[base0 + m1]     = l00;
                    g_vth[base1 + m1]     = h01;  g_vtl[base1 + m1]     = l01;
                    g_vth[base0 + m1 + 8] = h10;  g_vtl[base0 + m1 + 8] = l10;
                    g_vth[base1 + m1 + 8] = h11;  g_vtl[base1 + m1 + 8] = l11;
                } else {
                    __nv_bfloat16* dh = (part == 0) ? g_qh : g_kh;
                    __nv_bfloat16* dl = (part == 0) ? g_ql : g_kl;
                    long a0 = (long)(hh * SEQ + m1) * DH + dd;
                    long a1 = (long)(hh * SEQ + m1 + 8) * DH + dd;
                    *(__nv_bfloat162*)(dh + a0) = __nv_bfloat162(h00, h01);
                    *(__nv_bfloat162*)(dl + a0) = __nv_bfloat162(l00, l01);
                    *(__nv_bfloat162*)(dh + a1) = __nv_bfloat162(h10, h11);
                    *(__nv_bfloat162*)(dl + a1) = __nv_bfloat162(l10, l11);
                }
            } else {
                *(float2*)(outp + (long)m1 * Ncols + n) = make_float2(v00, v01);
                *(float2*)(outp + (long)(m1 + 8) * Ncols + n) = make_float2(v10, v11);
            }
        }
    }
}

// ---------------------------------------------------------------------------
// Tensor-core flash attention, cp.async double-buffered B ([K;Eband]) and Vt.
// Prefetch for tile jt+1 is issued right after the head wait+sync, overlapping
// the whole scores-MMA + softmax + PV body of tile jt.
// ---------------------------------------------------------------------------
#define AT_QH 0
#define AT_QL 8192
#define AT_B0 16384                       // per stage: BH(24576) + BL(24576)
#define AT_BSTAGE 49152
#define AT_V0 (AT_B0 + 2 * AT_BSTAGE)     // 114688; per stage VH(8192)+VL(8192)
#define AT_VSTAGE 16384
#define AT_S  (AT_V0 + 2 * AT_VSTAGE)     // 147456: 64 x 196 fp32
#define AT_PH (AT_S + 50176)              // 197632
#define AT_PL (AT_PH + 8192)              // 205824
#define AT_ALPHA (AT_PL + 8192)           // 214016
#define AT_LS (AT_ALPHA + 256)
#define AT_SMEM (AT_LS + 256)             // 214528

__global__ __launch_bounds__(256, 1) void attn_tc() {
    extern __shared__ char smc[];
    const uint32_t sb = smem_u32(smc);
    float* S = (float*)(smc + AT_S);
    float* alpha_s = (float*)(smc + AT_ALPHA);
    float* l_s = (float*)(smc + AT_LS);

    const int tid = threadIdx.x;
    const int w = tid >> 5, lane = tid & 31;
    const int bid = blockIdx.x;
    const int it = 31 - (bid >> 4);       // big tiles first
    const int h = bid & 15;
    const int i0 = it * 64;
    const int tx = tid & 15, ty = tid >> 4;

    const int aq = lane >> 3, ar = lane & 7;
    const int a_row_off = (aq & 1) * 8 + ar;
    const int a_k_off   = (aq >> 1) * 8;
    const int bq = (lane >> 3) & 1, br = lane & 7;
    const int r0 = lane >> 2, c0 = (lane & 3) * 2;

    // Q tile via cp.async too (overlaps with first B/V prefetch)
    #pragma unroll
    for (int i2 = 0; i2 < 2; i2++) {
        int idx = tid + i2 * 256;
        int row = idx >> 3, ch = idx & 7;
        uint32_t soff = swz128((uint32_t)(row * 128 + ch * 16));
        long src = (long)(h * SEQ + i0 + row) * DH + ch * 8;
        cpa16(sb + AT_QH + soff, g_qh + src);
        cpa16(sb + AT_QL + soff, g_ql + src);
    }

    // prefetch helper (B + V for tile jt into stage jt&1)
    auto prefetch = [&](int jt) {
        const int j0 = jt * 64;
        const int mb = 1984 - i0 + j0;
        const uint32_t bs = sb + AT_B0 + (jt & 1) * AT_BSTAGE;
        #pragma unroll
        for (int i2 = 0; i2 < 6; i2++) {
            int idx = tid + i2 * 256;
            int row = idx >> 3, ch = idx & 7;
            uint32_t soff = swz128((uint32_t)(row * 128 + ch * 16));
            if (row < 64) {
                long src = (long)(h * SEQ + j0 + row) * DH + ch * 8;
                cpa16(bs + soff, g_kh + src);
                cpa16(bs + 24576 + soff, g_kl + src);
            } else {
                int m = mb + row - 64;
                int sz = (m < SEQ) ? 16 : 0;
                int mc = (m < SEQ) ? m : (SEQ - 1);
                long src = (long)(h * SEQ + mc) * DH + ch * 8;
                cpa16z(bs + soff, g_eh + src, sz);
                cpa16z(bs + 24576 + soff, g_el + src, sz);
            }
        }
        const uint32_t vs = sb + AT_V0 + (jt & 1) * AT_VSTAGE;
        #pragma unroll
        for (int i2 = 0; i2 < 2; i2++) {
            int idx = tid + i2 * 256;
            int row = idx >> 3, ch = idx & 7;
            uint32_t soff = swz128((uint32_t)(row * 128 + ch * 16));
            long src = (long)(h * DH + row) * SEQ + j0 + ch * 8;
            cpa16(vs + soff, g_vth + src);
            cpa16(vs + 8192 + soff, g_vtl + src);
        }
        cpa_commit();
    };

    prefetch(0);

    float m_i[4], l_i[4];
    #pragma unroll
    for (int i = 0; i < 4; i++) { m_i[i] = -1e30f; l_i[i] = 0.f; }
    float accO[4][4] = {};

    const int ntiles = it + 1;
    for (int jt = 0; jt < ntiles; jt++) {
        const int j0 = jt * 64;
        const uint32_t bst = sb + AT_B0 + (jt & 1) * AT_BSTAGE;
        const uint32_t vst = sb + AT_V0 + (jt & 1) * AT_VSTAGE;

        cpa_wait<0>();
        __syncthreads();

        // start next tile's copies now — stage alt is fully retired
        if (jt + 1 < ntiles) prefetch(jt + 1);

        // ---- scores MMA: S[64x192], warp w covers cols [w*24, w*24+24) ----
        float sacc[4][3][4] = {};
        #pragma unroll
        for (int ks = 0; ks < 4; ks++) {
            const int kk = ks * 16;
            uint32_t ah[4][4], al4[4][4], bh[3][2], bl[3][2];
            #pragma unroll
            for (int mf = 0; mf < 4; mf++) {
                int row = mf * 16 + a_row_off;
                uint32_t off = swz128((uint32_t)(row * 128 + (kk + a_k_off) * 2));
                ldm_x4(ah[mf], sb + AT_QH + off);
                ldm_x4(al4[mf], sb + AT_QL + off);
            }
            #pragma unroll
            for (int nf = 0; nf < 3; nf++) {
                int row = w * 24 + nf * 8 + br;
                uint32_t off = swz128((uint32_t)(row * 128 + (kk + bq * 8) * 2));
                ldm_x2(bh[nf], bst + off);
                ldm_x2(bl[nf], bst + 24576 + off);
            }
            #pragma unroll
            for (int mf = 0; mf < 4; mf++)
                #pragma unroll
                for (int nf = 0; nf < 3; nf++) {
                    mma_bf16(sacc[mf][nf], ah[mf], bh[nf]);
                    mma_bf16(sacc[mf][nf], ah[mf], bl[nf]);
                    mma_bf16(sacc[mf][nf], al4[mf], bh[nf]);
                }
        }
        #pragma unroll
        for (int mf = 0; mf < 4; mf++)
            #pragma unroll
            for (int nf = 0; nf < 3; nf++) {
                int cc = w * 24 + nf * 8 + c0;
                *(float2*)&S[(mf * 16 + r0) * 196 + cc] =
                    make_float2(sacc[mf][nf][0], sacc[mf][nf][1]);
                *(float2*)&S[(mf * 16 + r0 + 8) * 196 + cc] =
                    make_float2(sacc[mf][nf][2], sacc[mf][nf][3]);
            }
        __syncthreads();

        // ---- softmax ----
        #pragma unroll
        for (int i = 0; i < 4; i++) {
            int r = ty * 4 + i;
            int gi = i0 + r;
            float4 s1 = *(float4*)&S[r * 196 + tx * 4];
            int b2 = r * 196 + 127 - r + tx * 4;
            float sv[4];
            sv[0] = s1.x + S[b2];     sv[1] = s1.y + S[b2 + 1];
            sv[2] = s1.z + S[b2 + 2]; sv[3] = s1.w + S[b2 + 3];
            float rmax = -1e30f;
            #pragma unroll
            for (int c = 0; c < 4; c++) {
                int gj = j0 + tx * 4 + c;
                float s = (gj <= gi) ? sv[c] * 0.125f : -10000.0f;
                sv[c] = s;
                rmax = fmaxf(rmax, s);
            }
            #pragma unroll
            for (int off = 1; off < 16; off <<= 1)
                rmax = fmaxf(rmax, __shfl_xor_sync(0xffffffffu, rmax, off));
            float newm = fmaxf(m_i[i], rmax);
            float alpha = __expf(m_i[i] - newm);
            m_i[i] = newm;
            float ps = 0.f;
            #pragma unroll
            for (int c = 0; c < 4; c++) {
                sv[c] = __expf(sv[c] - newm);
                ps += sv[c];
            }
            #pragma unroll
            for (int off = 1; off < 16; off <<= 1)
                ps += __shfl_xor_sync(0xffffffffu, ps, off);
            l_i[i] = l_i[i] * alpha + ps;
            if (tx == 0) alpha_s[r] = alpha;
            __nv_bfloat16 ph[4], pl[4];
            #pragma unroll
            for (int c = 0; c < 4; c++) {
                ph[c] = __float2bfloat16(sv[c]);
                pl[c] = __float2bfloat16(sv[c] - __bfloat162float(ph[c]));
            }
            uint32_t poff = swz128((uint32_t)(r * 128 + tx * 8));
            *(__nv_bfloat162*)(smc + AT_PH + poff)     = __nv_bfloat162(ph[0], ph[1]);
            *(__nv_bfloat162*)(smc + AT_PH + poff + 4) = __nv_bfloat162(ph[2], ph[3]);
            *(__nv_bfloat162*)(smc + AT_PL + poff)     = __nv_bfloat162(pl[0], pl[1]);
            *(__nv_bfloat162*)(smc + AT_PL + poff + 4) = __nv_bfloat162(pl[2], pl[3]);
        }
        __syncthreads();

        // ---- PV MMA: warp w -> m-range (w&3)*16, n-range (w>>2)*32 ----
        float a0 = alpha_s[(w & 3) * 16 + r0];
        float a1 = alpha_s[(w & 3) * 16 + r0 + 8];
        #pragma unroll
        for (int nf = 0; nf < 4; nf++) {
            accO[nf][0] *= a0; accO[nf][1] *= a0;
            accO[nf][2] *= a1; accO[nf][3] *= a1;
        }
        #pragma unroll
        for (int ks = 0; ks < 4; ks++) {
            const int kk = ks * 16;
            uint32_t ph[4], pl4[4], vh[4][2], vl[4][2];
            int arow = (w & 3) * 16 + a_row_off;
            uint32_t aoff = swz128((uint32_t)(arow * 128 + (kk + a_k_off) * 2));
            ldm_x4(ph, sb + AT_PH + aoff);
            ldm_x4(pl4, sb + AT_PL + aoff);
            #pragma unroll
            for (int nf = 0; nf < 4; nf++) {
                int row = (w >> 2) * 32 + nf * 8 + br;
                uint32_t off = swz128((uint32_t)(row * 128 + (kk + bq * 8) * 2));
                ldm_x2(vh[nf], vst + off);
                ldm_x2(vl[nf], vst + 8192 + off);
            }
            #pragma unroll
            for (int nf = 0; nf < 4; nf++) {
                mma_bf16(accO[nf], ph, vh[nf]);
                mma_bf16(accO[nf], ph, vl[nf]);
                mma_bf16(accO[nf], pl4, vh[nf]);
            }
        }
    }

    // ---- epilogue: normalize, split to bf16, write ctx ----
    if (tx == 0) {
        #pragma unroll
        for (int i = 0; i < 4; i++) l_s[ty * 4 + i] = l_i[i];
    }
    __syncthreads();
    {
        int rr0 = (w & 3) * 16 + r0;
        float inv0 = 1.0f / l_s[rr0];
        float inv1 = 1.0f / l_s[rr0 + 8];
        #pragma unroll
        for (int nf = 0; nf < 4; nf++) {
            int c = (w >> 2) * 32 + nf * 8 + c0;
            int col = h * DH + c;
            float o00 = accO[nf][0] * inv0, o01 = accO[nf][1] * inv0;
            float o10 = accO[nf][2] * inv1, o11 = accO[nf][3] * inv1;
            __nv_bfloat16 h00 = __float2bfloat16(o00), h01 = __float2bfloat16(o01);
            __nv_bfloat16 h10 = __float2bfloat16(o10), h11 = __float2bfloat16(o11);
            __nv_bfloat16 l00 = __float2bfloat16(o00 - __bfloat162float(h00));
            __nv_bfloat16 l01 = __float2bfloat16(o01 - __bfloat162float(h01));
            __nv_bfloat16 l10 = __float2bfloat16(o10 - __bfloat162float(h10));
            __nv_bfloat16 l11 = __float2bfloat16(o11 - __bfloat162float(h11));
            long a0 = (long)(i0 + rr0) * HID + col;
            long a1 = (long)(i0 + rr0 + 8) * HID + col;
            *(__nv_bfloat162*)(g_cth + a0) = __nv_bfloat162(h00, h01);
            *(__nv_bfloat162*)(g_ctl + a0) = __nv_bfloat162(l00, l01);
            *(__nv_bfloat162*)(g_cth + a1) = __nv_bfloat162(h10, h11);
            *(__nv_bfloat162*)(g_ctl + a1) = __nv_bfloat162(l10, l11);
        }
    }
}

// ---------------------------------------------------------------------------

extern "C" void kernel_launch(void* const* d_in, const int* in_sizes, int n_in,
                              void* d_out, int out_size) {
    const float* x   = (const float*)d_in[0];
    const float* caw = (const float*)d_in[1];
    const float* cab = (const float*)d_in[2];
    const float* cpw = (const float*)d_in[3];
    const float* cpb = (const float*)d_in[4];
    const float* E   = (const float*)d_in[5];
    float* out = (float*)d_out;

    cudaFuncSetAttribute(gemm_tc<0>, cudaFuncAttributeMaxDynamicSharedMemorySize, SM_GEMM);
    cudaFuncSetAttribute(gemm_tc<1>, cudaFuncAttributeMaxDynamicSharedMemorySize, SM_GEMM);
    cudaFuncSetAttribute(attn_tc, cudaFuncAttributeMaxDynamicSharedMemorySize, AT_SMEM);

    __nv_bfloat16 *xh, *xl, *eh, *el, *wah, *wal, *wph, *wpl, *cth, *ctl;
    cudaGetSymbolAddress((void**)&xh,  g_xh);
    cudaGetSymbolAddress((void**)&xl,  g_xl);
    cudaGetSymbolAddress((void**)&eh,  g_eh);
    cudaGetSymbolAddress((void**)&el,  g_el);
    cudaGetSymbolAddress((void**)&wah, g_wah);
    cudaGetSymbolAddress((void**)&wal, g_wal);
    cudaGetSymbolAddress((void**)&wph, g_wph);
    cudaGetSymbolAddress((void**)&wpl, g_wpl);
    cudaGetSymbolAddress((void**)&cth, g_cth);
    cudaGetSymbolAddress((void**)&ctl, g_ctl);

    split_kernel<<<(SEQ * HID) / 1024, 256>>>(x, xh, xl, SEQ * HID);
    split_kernel<<<(NH * SEQ * DH) / 1024, 256>>>(E, eh, el, NH * SEQ * DH);
    transpose_split_kernel<<<dim3(N_QKV / 32, HID / 32), dim3(32, 8)>>>(caw, wah, wal, HID, N_QKV);
    transpose_split_kernel<<<dim3(HID / 32, HID / 32), dim3(32, 8)>>>(cpw, wph, wpl, HID, HID);

    gemm_tc<0><<<dim3(N_QKV / 128, SEQ / 128), 256, SM_GEMM>>>(xh, xl, wah, wal,
                                                               cab, nullptr, N_QKV);
    attn_tc<<<dim3(NH * 32), 256, AT_SMEM>>>();

    gemm_tc<1><<<dim3(HID / 128, SEQ / 128), 256, SM_GEMM>>>(cth, ctl, wph, wpl,
                                                             cpb, out, HID);
}